// round 1
// baseline (speedup 1.0000x reference)
#include <cuda_runtime.h>
#include <cuda_bf16.h>
#include <cstdint>

#define B_  4
#define S_  2048
#define HID_ 2048
#define NH_ 16
#define NKV_ 4
#define D_  128
#define EPS_ 1e-6f
#define SCALE_ 0.08838834764831845f   // 128^-0.5

// ---------------- scratch (static __device__, allocation-free) ----------------
__device__ float g_qg  [(size_t)B_*S_*NH_*2*D_];   // (b,s,h,2D)  33.5M
__device__ float g_q   [(size_t)B_*NH_*S_*D_];     // (b,h,s,d)   16.7M
__device__ float g_ktmp[(size_t)B_*S_*NKV_*D_];    // (b,s,kh,d)   4.2M
__device__ float g_k   [(size_t)B_*NKV_*S_*D_];    // (b,kh,s,d)   4.2M
__device__ float g_v   [(size_t)B_*S_*NKV_*D_];    // (b,s,kh,d)   4.2M
__device__ float g_octx[(size_t)B_*S_*NH_*D_];     // (b,s,h,d)   16.7M
__device__ float g_rowmax[(size_t)B_*NH_*S_];
__device__ float g_rowsum[(size_t)B_*NH_*S_];

// ---------------- generic fp32 GEMM: C[M,N] = A[M,K] @ B[K,N] ----------------
// BM=BN=64, BK=16, 256 threads, each thread computes 4x4.
__global__ __launch_bounds__(256) void sgemm(const float* __restrict__ A,
                                             const float* __restrict__ Bm,
                                             float* __restrict__ C,
                                             int M, int N, int K) {
    __shared__ float As[16][64];
    __shared__ float Bs[16][64];
    const int tid = threadIdx.x;
    const int bx = blockIdx.x, by = blockIdx.y;
    const int arow = tid >> 2, acol = (tid & 3) * 4;
    const int brow = tid >> 4, bcol = (tid & 15) * 4;
    const int ty = tid >> 4, tx = tid & 15;

    const float* Aptr = A + (size_t)(by * 64 + arow) * K + acol;
    const float* Bptr = Bm + (size_t)brow * N + bx * 64 + bcol;

    float acc[4][4] = {};
    for (int k0 = 0; k0 < K; k0 += 16) {
        float4 av = *(const float4*)(Aptr + k0);
        As[acol + 0][arow] = av.x;
        As[acol + 1][arow] = av.y;
        As[acol + 2][arow] = av.z;
        As[acol + 3][arow] = av.w;
        *(float4*)&Bs[brow][bcol] = *(const float4*)(Bptr + (size_t)k0 * N);
        __syncthreads();
#pragma unroll
        for (int kk = 0; kk < 16; kk++) {
            float4 a = *(const float4*)&As[kk][ty * 4];
            float4 b = *(const float4*)&Bs[kk][tx * 4];
            acc[0][0] += a.x * b.x; acc[0][1] += a.x * b.y; acc[0][2] += a.x * b.z; acc[0][3] += a.x * b.w;
            acc[1][0] += a.y * b.x; acc[1][1] += a.y * b.y; acc[1][2] += a.y * b.z; acc[1][3] += a.y * b.w;
            acc[2][0] += a.z * b.x; acc[2][1] += a.z * b.y; acc[2][2] += a.z * b.z; acc[2][3] += a.z * b.w;
            acc[3][0] += a.w * b.x; acc[3][1] += a.w * b.y; acc[3][2] += a.w * b.z; acc[3][3] += a.w * b.w;
        }
        __syncthreads();
    }
    float* Cptr = C + (size_t)(by * 64 + ty * 4) * N + bx * 64 + tx * 4;
#pragma unroll
    for (int i = 0; i < 4; i++) {
        float4 cv = make_float4(acc[i][0], acc[i][1], acc[i][2], acc[i][3]);
        *(float4*)(Cptr + (size_t)i * N) = cv;
    }
}

// ---------------- RMSNorm + RoPE for Q (also leaves gate in g_qg) ----------------
__global__ __launch_bounds__(128) void norm_rope_q(const float* __restrict__ qg,
                                                   const float* __restrict__ cosb,
                                                   const float* __restrict__ sinb,
                                                   const float* __restrict__ w,
                                                   float* __restrict__ qout) {
    const int idx = blockIdx.x;            // b*S*NH + s*NH + h
    const int h = idx % NH_;
    const int bs = idx / NH_;              // b*S + s
    const int d = threadIdx.x;
    const float* x = qg + ((size_t)bs * NH_ + h) * (2 * D_);
    float xv = x[d];
    float sq = xv * xv;
#pragma unroll
    for (int o = 16; o > 0; o >>= 1) sq += __shfl_xor_sync(0xffffffffu, sq, o);
    __shared__ float wsum[4];
    __shared__ float xs[D_];
    if ((d & 31) == 0) wsum[d >> 5] = sq;
    __syncthreads();
    float total = wsum[0] + wsum[1] + wsum[2] + wsum[3];
    float xn = xv * rsqrtf(total * (1.0f / D_) + EPS_) * (1.0f + w[d]);
    xs[d] = xn;
    __syncthreads();
    float c = cosb[(size_t)bs * D_ + d];
    float sn = sinb[(size_t)bs * D_ + d];
    float rot = (d < D_ / 2) ? -xs[d + D_ / 2] : xs[d - D_ / 2];
    const int b = bs / S_, s = bs % S_;
    qout[(((size_t)b * NH_ + h) * S_ + s) * D_ + d] = xn * c + rot * sn;
}

__global__ __launch_bounds__(128) void norm_rope_k(const float* __restrict__ kin,
                                                   const float* __restrict__ cosb,
                                                   const float* __restrict__ sinb,
                                                   const float* __restrict__ w,
                                                   float* __restrict__ kout) {
    const int idx = blockIdx.x;            // b*S*NKV + s*NKV + kh
    const int kh = idx % NKV_;
    const int bs = idx / NKV_;
    const int d = threadIdx.x;
    const float* x = kin + ((size_t)bs * NKV_ + kh) * D_;
    float xv = x[d];
    float sq = xv * xv;
#pragma unroll
    for (int o = 16; o > 0; o >>= 1) sq += __shfl_xor_sync(0xffffffffu, sq, o);
    __shared__ float wsum[4];
    __shared__ float xs[D_];
    if ((d & 31) == 0) wsum[d >> 5] = sq;
    __syncthreads();
    float total = wsum[0] + wsum[1] + wsum[2] + wsum[3];
    float xn = xv * rsqrtf(total * (1.0f / D_) + EPS_) * (1.0f + w[d]);
    xs[d] = xn;
    __syncthreads();
    float c = cosb[(size_t)bs * D_ + d];
    float sn = sinb[(size_t)bs * D_ + d];
    float rot = (d < D_ / 2) ? -xs[d + D_ / 2] : xs[d - D_ / 2];
    const int b = bs / S_, s = bs % S_;
    kout[(((size_t)b * NKV_ + kh) * S_ + s) * D_ + d] = xn * c + rot * sn;
}

// ---------------- attention pass 1: per-row max & sumexp (causal) ----------------
__global__ __launch_bounds__(256) void attn_stats(const float* __restrict__ q,
                                                  const float* __restrict__ k,
                                                  float* __restrict__ rowmax,
                                                  float* __restrict__ rowsum) {
    const int qt = blockIdx.x, bh = blockIdx.y;
    const int b = bh >> 4, h = bh & 15, kh = h >> 2;
    __shared__ float Qs[32][D_ + 4];
    __shared__ float Ks[32][D_ + 4];
    const int tid = threadIdx.x;
    const int q0 = qt * 32;
    {   // load Q tile
        int rr = tid >> 3, c0 = (tid & 7) * 16;
        const float* qb = q + (((size_t)b * NH_ + h) * S_ + q0 + rr) * D_;
#pragma unroll
        for (int u = 0; u < 4; u++)
            *(float4*)&Qs[rr][c0 + u * 4] = *(const float4*)(qb + c0 + u * 4);
    }
    const float* kbase = k + (((size_t)b * NKV_ + kh) * S_) * D_;
    const int r = tid >> 3, jo = tid & 7;
    const int gi = q0 + r;
    float m = -1e30f, l = 0.0f;
    for (int kt = 0; kt <= qt; kt++) {
        __syncthreads();
        {
            int rr = tid >> 3, c0 = (tid & 7) * 16;
            const float* kb = kbase + (size_t)(kt * 32 + rr) * D_;
#pragma unroll
            for (int u = 0; u < 4; u++)
                *(float4*)&Ks[rr][c0 + u * 4] = *(const float4*)(kb + c0 + u * 4);
        }
        __syncthreads();
#pragma unroll
        for (int jj = 0; jj < 4; jj++) {
            int j = jo + jj * 8;
            int gj = kt * 32 + j;
            if (gj <= gi) {
                float acc = 0.0f;
#pragma unroll
                for (int dd = 0; dd < D_; dd += 4) {
                    float4 qv = *(const float4*)&Qs[r][dd];
                    float4 kv = *(const float4*)&Ks[j][dd];
                    acc += qv.x * kv.x + qv.y * kv.y + qv.z * kv.z + qv.w * kv.w;
                }
                float x = acc * SCALE_;
                if (x > m) { l = l * __expf(m - x) + 1.0f; m = x; }
                else       { l += __expf(x - m); }
            }
        }
    }
#pragma unroll
    for (int o = 1; o < 8; o <<= 1) {
        float m2 = __shfl_xor_sync(0xffffffffu, m, o);
        float l2 = __shfl_xor_sync(0xffffffffu, l, o);
        float mn = fmaxf(m, m2);
        l = l * __expf(m - mn) + l2 * __expf(m2 - mn);
        m = mn;
    }
    if (jo == 0) {
        rowmax[(size_t)bh * S_ + gi] = m;
        rowsum[(size_t)bh * S_ + gi] = l;
    }
}

// ---------------- attention pass 2: write normalized P + accumulate PV ----------------
__global__ __launch_bounds__(256) void attn_out(const float* __restrict__ q,
                                                const float* __restrict__ k,
                                                const float* __restrict__ v,
                                                const float* __restrict__ rowmax,
                                                const float* __restrict__ rowsum,
                                                float* __restrict__ P,
                                                float* __restrict__ octx) {
    const int qt = blockIdx.x, bh = blockIdx.y;
    const int b = bh >> 4, h = bh & 15, kh = h >> 2;
    __shared__ float Qs[32][D_ + 4];
    __shared__ float KVs[32][D_ + 4];
    __shared__ float Ps[32][36];
    const int tid = threadIdx.x;
    const int q0 = qt * 32;
    {   // load Q tile
        int rr = tid >> 3, c0 = (tid & 7) * 16;
        const float* qb = q + (((size_t)b * NH_ + h) * S_ + q0 + rr) * D_;
#pragma unroll
        for (int u = 0; u < 4; u++)
            *(float4*)&Qs[rr][c0 + u * 4] = *(const float4*)(qb + c0 + u * 4);
    }
    const float* kbase = k + (((size_t)b * NKV_ + kh) * S_) * D_;
    const int r = tid >> 3, g = tid & 7;
    const int gi = q0 + r;
    const float m = rowmax[(size_t)bh * S_ + gi];
    const float invl = 1.0f / rowsum[(size_t)bh * S_ + gi];
    float4 o0 = {0,0,0,0}, o1 = {0,0,0,0}, o2 = {0,0,0,0}, o3 = {0,0,0,0};

    for (int kt = 0; kt <= qt; kt++) {
        __syncthreads();
        {   // K tile
            int rr = tid >> 3, c0 = (tid & 7) * 16;
            const float* kb = kbase + (size_t)(kt * 32 + rr) * D_;
#pragma unroll
            for (int u = 0; u < 4; u++)
                *(float4*)&KVs[rr][c0 + u * 4] = *(const float4*)(kb + c0 + u * 4);
        }
        __syncthreads();
#pragma unroll
        for (int jj = 0; jj < 4; jj++) {
            int j = g + jj * 8;
            int gj = kt * 32 + j;
            float p = 0.0f;
            if (gj <= gi) {
                float acc = 0.0f;
#pragma unroll
                for (int dd = 0; dd < D_; dd += 4) {
                    float4 qv = *(const float4*)&Qs[r][dd];
                    float4 kv = *(const float4*)&KVs[j][dd];
                    acc += qv.x * kv.x + qv.y * kv.y + qv.z * kv.z + qv.w * kv.w;
                }
                p = __expf(acc * SCALE_ - m) * invl;
            }
            Ps[r][j] = p;
        }
        __syncthreads();
        {   // coalesced P write from smem
            int rr = tid >> 3, c0 = (tid & 7) * 4;
            float4 pv = *(const float4*)&Ps[rr][c0];
            *(float4*)(P + ((size_t)bh * S_ + q0 + rr) * S_ + kt * 32 + c0) = pv;
        }
        {   // V tile (reuse KVs)
            int rr = tid >> 3, c0 = (tid & 7) * 16;
            const float* vb = v + (((size_t)b * S_ + kt * 32 + rr) * NKV_ + kh) * D_;
#pragma unroll
            for (int u = 0; u < 4; u++)
                *(float4*)&KVs[rr][c0 + u * 4] = *(const float4*)(vb + c0 + u * 4);
        }
        __syncthreads();
#pragma unroll
        for (int j = 0; j < 32; j++) {
            float pv = Ps[r][j];
            float4 v0 = *(const float4*)&KVs[j][0 * 32 + g * 4];
            float4 v1 = *(const float4*)&KVs[j][1 * 32 + g * 4];
            float4 v2 = *(const float4*)&KVs[j][2 * 32 + g * 4];
            float4 v3 = *(const float4*)&KVs[j][3 * 32 + g * 4];
            o0.x += pv * v0.x; o0.y += pv * v0.y; o0.z += pv * v0.z; o0.w += pv * v0.w;
            o1.x += pv * v1.x; o1.y += pv * v1.y; o1.z += pv * v1.z; o1.w += pv * v1.w;
            o2.x += pv * v2.x; o2.y += pv * v2.y; o2.z += pv * v2.z; o2.w += pv * v2.w;
            o3.x += pv * v3.x; o3.y += pv * v3.y; o3.z += pv * v3.z; o3.w += pv * v3.w;
        }
    }
    float* ob = octx + (((size_t)b * S_ + gi) * NH_ + h) * D_;
    *(float4*)(ob + 0 * 32 + g * 4) = o0;
    *(float4*)(ob + 1 * 32 + g * 4) = o1;
    *(float4*)(ob + 2 * 32 + g * 4) = o2;
    *(float4*)(ob + 3 * 32 + g * 4) = o3;
}

// ---------------- zero-fill fully-masked P tiles ----------------
__global__ __launch_bounds__(128) void zero_upper(float* __restrict__ P) {
    const int row = blockIdx.x;          // bh*S + i
    const int i = row & (S_ - 1);
    const int jstart = ((i >> 5) + 1) << 5;
    float* p = P + (size_t)row * S_;
    const float4 z = {0, 0, 0, 0};
    for (int j = jstart + threadIdx.x * 4; j < S_; j += blockDim.x * 4)
        *(float4*)(p + j) = z;
}

// ---------------- gate: octx *= sigmoid(gate) ----------------
__global__ __launch_bounds__(256) void gate_mul(const float* __restrict__ qg,
                                                float* __restrict__ octx) {
    size_t i4 = (size_t)blockIdx.x * blockDim.x + threadIdx.x;   // float4 index
    size_t e = i4 * 4;
    int d = (int)(e % D_);
    int h = (int)((e / D_) % NH_);
    size_t bs = e / (D_ * NH_);
    const float4 gv = *(const float4*)(qg + (bs * NH_ + h) * (2 * D_) + D_ + d);
    float4 ov = *(float4*)(octx + e);
    ov.x *= 1.0f / (1.0f + expf(-gv.x));
    ov.y *= 1.0f / (1.0f + expf(-gv.y));
    ov.z *= 1.0f / (1.0f + expf(-gv.z));
    ov.w *= 1.0f / (1.0f + expf(-gv.w));
    *(float4*)(octx + e) = ov;
}

// ---------------- launch ----------------
extern "C" void kernel_launch(void* const* d_in, const int* in_sizes, int n_in,
                              void* d_out, int out_size) {
    const float* hidden = (const float*)d_in[0];
    const float* cosb   = (const float*)d_in[1];
    const float* sinb   = (const float*)d_in[2];
    // d_in[3] = attention_mask (causal handled analytically)
    const float* Wq     = (const float*)d_in[4];
    const float* Wk     = (const float*)d_in[5];
    const float* Wv     = (const float*)d_in[6];
    const float* Wo     = (const float*)d_in[7];
    const float* qnw    = (const float*)d_in[8];
    const float* knw    = (const float*)d_in[9];

    float* out = (float*)d_out;
    const size_t ao_elems = (size_t)B_ * S_ * HID_;     // 16,777,216
    float* P = out + ao_elems;                          // attn_weights region

    float *qg, *qbuf, *ktmp, *kbuf, *vbuf, *octx, *rmax, *rsum;
    cudaGetSymbolAddress((void**)&qg,   g_qg);
    cudaGetSymbolAddress((void**)&qbuf, g_q);
    cudaGetSymbolAddress((void**)&ktmp, g_ktmp);
    cudaGetSymbolAddress((void**)&kbuf, g_k);
    cudaGetSymbolAddress((void**)&vbuf, g_v);
    cudaGetSymbolAddress((void**)&octx, g_octx);
    cudaGetSymbolAddress((void**)&rmax, g_rowmax);
    cudaGetSymbolAddress((void**)&rsum, g_rowsum);

    const int M = B_ * S_;   // 8192
    // projections
    sgemm<<<dim3((NH_ * 2 * D_) / 64, M / 64), 256>>>(hidden, Wq, qg, M, NH_ * 2 * D_, HID_);
    sgemm<<<dim3((NKV_ * D_) / 64, M / 64), 256>>>(hidden, Wk, ktmp, M, NKV_ * D_, HID_);
    sgemm<<<dim3((NKV_ * D_) / 64, M / 64), 256>>>(hidden, Wv, vbuf, M, NKV_ * D_, HID_);
    // norm + rope
    norm_rope_q<<<B_ * S_ * NH_, 128>>>(qg, cosb, sinb, qnw, qbuf);
    norm_rope_k<<<B_ * S_ * NKV_, 128>>>(ktmp, cosb, sinb, knw, kbuf);
    // attention
    attn_stats<<<dim3(S_ / 32, B_ * NH_), 256>>>(qbuf, kbuf, rmax, rsum);
    attn_out<<<dim3(S_ / 32, B_ * NH_), 256>>>(qbuf, kbuf, vbuf, rmax, rsum, P, octx);
    zero_upper<<<B_ * NH_ * S_, 128>>>(P);
    // gate + output projection
    gate_mul<<<(int)(((size_t)B_ * S_ * NH_ * D_ / 4) / 256), 256>>>(qg, octx);
    sgemm<<<dim3(HID_ / 64, M / 64), 256>>>(octx, Wo, out, M, HID_, HID_);
}

// round 3
// speedup vs baseline: 1.3352x; 1.3352x over previous
#include <cuda_runtime.h>
#include <cuda_bf16.h>
#include <cstdint>

#define B_  4
#define S_  2048
#define HID_ 2048
#define NH_ 16
#define NKV_ 4
#define D_  128
#define EPS_ 1e-6f
#define SCALE_ 0.08838834764831845f   // 128^-0.5

#define MT_  8192     // B*S rows
#define KK_  2048     // GEMM K (always HID_)

// ---------------- scratch (static __device__, allocation-free) ----------------
__device__ float g_qg  [(size_t)MT_*4096];         // (b,s,h,2D)
__device__ float g_q   [(size_t)B_*NH_*S_*D_];     // (b,h,s,d)
__device__ float g_ktmp[(size_t)MT_*512];          // (b,s,kh,d)
__device__ float g_k   [(size_t)B_*NKV_*S_*D_];    // (b,kh,s,d)
__device__ float g_v   [(size_t)MT_*512];          // (b,s,kh,d)
__device__ float g_octx[(size_t)MT_*2048];         // (b,s,h,d)
__device__ float g_rowmax[(size_t)B_*NH_*S_];
__device__ float g_rowsum[(size_t)B_*NH_*S_];
// bf16 hi/lo split buffers
__device__ __nv_bfloat16 g_ahi[(size_t)MT_*KK_],  g_alo[(size_t)MT_*KK_];
__device__ __nv_bfloat16 g_wqh[(size_t)4096*KK_], g_wql[(size_t)4096*KK_];
__device__ __nv_bfloat16 g_wkh[(size_t)512*KK_],  g_wkl[(size_t)512*KK_];
__device__ __nv_bfloat16 g_wvh[(size_t)512*KK_],  g_wvl[(size_t)512*KK_];
__device__ __nv_bfloat16 g_woh[(size_t)2048*KK_], g_wol[(size_t)2048*KK_];
__device__ __nv_bfloat16 g_ohi[(size_t)MT_*2048], g_olo[(size_t)MT_*2048];

// ================= PTX helpers (family-target-safe: sm_80+ features only) =====
__device__ __forceinline__ uint32_t smem_u32(const void* p) {
    uint32_t a;
    asm("{ .reg .u64 t; cvta.to.shared.u64 t, %1; cvt.u32.u64 %0, t; }" : "=r"(a) : "l"(p));
    return a;
}
__device__ __forceinline__ void cp16(uint32_t s, const void* g) {
    asm volatile("cp.async.cg.shared.global [%0], [%1], 16;" :: "r"(s), "l"(g));
}
__device__ __forceinline__ void ldm4(uint32_t* r, uint32_t addr) {
    asm volatile("ldmatrix.sync.aligned.m8n8.x4.shared.b16 {%0,%1,%2,%3}, [%4];"
                 : "=r"(r[0]), "=r"(r[1]), "=r"(r[2]), "=r"(r[3]) : "r"(addr));
}
__device__ __forceinline__ void mma_bf16(float* c, const uint32_t* a, const uint32_t* b) {
    asm volatile("mma.sync.aligned.m16n8k16.row.col.f32.bf16.bf16.f32 "
                 "{%0,%1,%2,%3}, {%4,%5,%6,%7}, {%8,%9}, {%0,%1,%2,%3};"
                 : "+f"(c[0]), "+f"(c[1]), "+f"(c[2]), "+f"(c[3])
                 : "r"(a[0]), "r"(a[1]), "r"(a[2]), "r"(a[3]), "r"(b[0]), "r"(b[1]));
}
// swizzled smem offset for a 128-col-byte row tile: row r (0..127), 16B chunk c (0..7)
__device__ __forceinline__ uint32_t phys(int r, int c) {
    return (uint32_t)(r * 128 + ((c ^ (r & 7)) << 4));
}

#define STG_BYTES 65536          // per pipeline stage: Ahi|Alo|Bhi|Blo, 16KB each
#define GEMM_SMEM (2 * STG_BYTES)

// ======= HMMA bf16x3-split GEMM: C[M,N] = A[M,K] * Bt[N,K]^T (M=8192,K=2048) ====
__global__ __launch_bounds__(256, 1) void gemm_bf16x3(
    const __nv_bfloat16* __restrict__ Ahi, const __nv_bfloat16* __restrict__ Alo,
    const __nv_bfloat16* __restrict__ Bhi, const __nv_bfloat16* __restrict__ Blo,
    float* __restrict__ C, int N) {
    extern __shared__ char smem[];
    const uint32_t sb = smem_u32(smem);
    const int tid = threadIdx.x, wid = tid >> 5, lane = tid & 31;
    const int m0 = blockIdx.y * 128, n0 = blockIdx.x * 128;
    const int NKI = KK_ / 64;    // 32 iters

    const __nv_bfloat16* ah = Ahi + (size_t)m0 * KK_;
    const __nv_bfloat16* al = Alo + (size_t)m0 * KK_;
    const __nv_bfloat16* bh = Bhi + (size_t)n0 * KK_;
    const __nv_bfloat16* bl = Blo + (size_t)n0 * KK_;

    auto load_stage = [&](int st, int it) {
        const uint32_t base = sb + st * STG_BYTES;
        const int k0 = it * 64;
        // 4 regions x 1024 chunks of 16B; q: region=q>>10, r=(q&1023)>>3, c=q&7
        for (int q = tid; q < 4096; q += 256) {
            int reg = q >> 10, qq = q & 1023;
            int r = qq >> 3, c = qq & 7;
            const __nv_bfloat16* src;
            switch (reg) {
                case 0: src = ah; break;
                case 1: src = al; break;
                case 2: src = bh; break;
                default: src = bl; break;
            }
            cp16(base + reg * 16384 + phys(r, c), src + (size_t)r * KK_ + k0 + c * 8);
        }
        asm volatile("cp.async.commit_group;" ::: "memory");
    };

    load_stage(0, 0);
    load_stage(1, 1);

    const int wm = (wid & 3) * 32;       // warp m offset within tile
    const int wn = (wid >> 2) * 64;      // warp n offset within tile
    float acc[2][8][4];
#pragma unroll
    for (int i = 0; i < 2; i++)
#pragma unroll
        for (int j = 0; j < 8; j++)
#pragma unroll
            for (int q = 0; q < 4; q++) acc[i][j][q] = 0.0f;

    const int fr = (lane & 7) + ((lane >> 3) & 1) * 8;   // ldmatrix row-within-16
    const int fc = lane >> 4;                            // ldmatrix k-chunk offset

    for (int i = 0; i < NKI; i++) {
        const int st = i & 1;
        if (i == NKI - 1) asm volatile("cp.async.wait_group 0;" ::: "memory");
        else              asm volatile("cp.async.wait_group 1;" ::: "memory");
        __syncthreads();

        const uint32_t bA = sb + st * STG_BYTES;
        const uint32_t bAl = bA + 16384, bB = bA + 32768, bBl = bA + 49152;
#pragma unroll
        for (int s = 0; s < 4; s++) {                    // four k16 steps
            uint32_t ahf[2][4], alf[2][4], bhf[8][2], blf[8][2];
#pragma unroll
            for (int mi = 0; mi < 2; mi++) {
                int r = wm + mi * 16 + fr;
                uint32_t off = phys(r, s * 2 + fc);
                ldm4(ahf[mi], bA + off);
                ldm4(alf[mi], bAl + off);
            }
#pragma unroll
            for (int ng = 0; ng < 4; ng++) {             // n16 groups
                int r = wn + ng * 16 + fr;
                uint32_t off = phys(r, s * 2 + fc);
                uint32_t t[4];
                ldm4(t, bB + off);
                bhf[ng * 2][0] = t[0]; bhf[ng * 2][1] = t[2];
                bhf[ng * 2 + 1][0] = t[1]; bhf[ng * 2 + 1][1] = t[3];
                ldm4(t, bBl + off);
                blf[ng * 2][0] = t[0]; blf[ng * 2][1] = t[2];
                blf[ng * 2 + 1][0] = t[1]; blf[ng * 2 + 1][1] = t[3];
            }
#pragma unroll
            for (int mi = 0; mi < 2; mi++)
#pragma unroll
                for (int n = 0; n < 8; n++) {
                    mma_bf16(acc[mi][n], ahf[mi], bhf[n]);
                    mma_bf16(acc[mi][n], ahf[mi], blf[n]);
                    mma_bf16(acc[mi][n], alf[mi], bhf[n]);
                }
        }
        __syncthreads();
        if (i + 2 < NKI) load_stage(st, i + 2);
    }

    // epilogue: direct stores (c0,c1 row r, c2,c3 row r+8; cols (lane&3)*2+{0,1})
#pragma unroll
    for (int mi = 0; mi < 2; mi++) {
        int r0 = m0 + wm + mi * 16 + (lane >> 2);
#pragma unroll
        for (int n = 0; n < 8; n++) {
            int col = n0 + wn + n * 8 + (lane & 3) * 2;
            *(float2*)(C + (size_t)r0 * N + col)       = make_float2(acc[mi][n][0], acc[mi][n][1]);
            *(float2*)(C + (size_t)(r0 + 8) * N + col) = make_float2(acc[mi][n][2], acc[mi][n][3]);
        }
    }
}

// ============ fp32 -> bf16 hi/lo split ============
__global__ __launch_bounds__(256) void split_bf16(const float* __restrict__ x,
                                                  __nv_bfloat16* __restrict__ hi,
                                                  __nv_bfloat16* __restrict__ lo,
                                                  int n4) {
    int i = blockIdx.x * 256 + threadIdx.x;
    if (i >= n4) return;
    float4 v = ((const float4*)x)[i];
    __nv_bfloat16 h0 = __float2bfloat16(v.x), h1 = __float2bfloat16(v.y);
    __nv_bfloat16 h2 = __float2bfloat16(v.z), h3 = __float2bfloat16(v.w);
    __nv_bfloat16 l0 = __float2bfloat16(v.x - __bfloat162float(h0));
    __nv_bfloat16 l1 = __float2bfloat16(v.y - __bfloat162float(h1));
    __nv_bfloat16 l2 = __float2bfloat16(v.z - __bfloat162float(h2));
    __nv_bfloat16 l3 = __float2bfloat16(v.w - __bfloat162float(h3));
    ((__nv_bfloat162*)hi)[2 * i]     = __nv_bfloat162(h0, h1);
    ((__nv_bfloat162*)hi)[2 * i + 1] = __nv_bfloat162(h2, h3);
    ((__nv_bfloat162*)lo)[2 * i]     = __nv_bfloat162(l0, l1);
    ((__nv_bfloat162*)lo)[2 * i + 1] = __nv_bfloat162(l2, l3);
}

// ============ W[K,N] fp32 -> Wt hi/lo bf16 [N,K] ============
__global__ __launch_bounds__(256) void transpose_split(const float* __restrict__ W,
                                                       __nv_bfloat16* __restrict__ thi,
                                                       __nv_bfloat16* __restrict__ tlo,
                                                       int N) {
    __shared__ float t[32][33];
    const int n0 = blockIdx.x * 32, k0 = blockIdx.y * 32;
    const int tx = threadIdx.x, ty = threadIdx.y;
    for (int i = ty; i < 32; i += 8)
        t[i][tx] = W[(size_t)(k0 + i) * N + n0 + tx];
    __syncthreads();
    for (int i = ty; i < 32; i += 8) {
        float v = t[tx][i];
        __nv_bfloat16 h = __float2bfloat16(v);
        __nv_bfloat16 l = __float2bfloat16(v - __bfloat162float(h));
        thi[(size_t)(n0 + i) * KK_ + k0 + tx] = h;
        tlo[(size_t)(n0 + i) * KK_ + k0 + tx] = l;
    }
}

// ---------------- RMSNorm + RoPE ----------------
__global__ __launch_bounds__(128) void norm_rope_q(const float* __restrict__ qg,
                                                   const float* __restrict__ cosb,
                                                   const float* __restrict__ sinb,
                                                   const float* __restrict__ w,
                                                   float* __restrict__ qout) {
    const int idx = blockIdx.x;
    const int h = idx % NH_;
    const int bs = idx / NH_;
    const int d = threadIdx.x;
    const float* x = qg + ((size_t)bs * NH_ + h) * (2 * D_);
    float xv = x[d];
    float sq = xv * xv;
#pragma unroll
    for (int o = 16; o > 0; o >>= 1) sq += __shfl_xor_sync(0xffffffffu, sq, o);
    __shared__ float wsum[4];
    __shared__ float xs[D_];
    if ((d & 31) == 0) wsum[d >> 5] = sq;
    __syncthreads();
    float total = wsum[0] + wsum[1] + wsum[2] + wsum[3];
    float xn = xv * rsqrtf(total * (1.0f / D_) + EPS_) * (1.0f + w[d]);
    xs[d] = xn;
    __syncthreads();
    float c = cosb[(size_t)bs * D_ + d];
    float sn = sinb[(size_t)bs * D_ + d];
    float rot = (d < D_ / 2) ? -xs[d + D_ / 2] : xs[d - D_ / 2];
    const int b = bs / S_, s = bs % S_;
    qout[(((size_t)b * NH_ + h) * S_ + s) * D_ + d] = xn * c + rot * sn;
}

__global__ __launch_bounds__(128) void norm_rope_k(const float* __restrict__ kin,
                                                   const float* __restrict__ cosb,
                                                   const float* __restrict__ sinb,
                                                   const float* __restrict__ w,
                                                   float* __restrict__ kout) {
    const int idx = blockIdx.x;
    const int kh = idx % NKV_;
    const int bs = idx / NKV_;
    const int d = threadIdx.x;
    const float* x = kin + ((size_t)bs * NKV_ + kh) * D_;
    float xv = x[d];
    float sq = xv * xv;
#pragma unroll
    for (int o = 16; o > 0; o >>= 1) sq += __shfl_xor_sync(0xffffffffu, sq, o);
    __shared__ float wsum[4];
    __shared__ float xs[D_];
    if ((d & 31) == 0) wsum[d >> 5] = sq;
    __syncthreads();
    float total = wsum[0] + wsum[1] + wsum[2] + wsum[3];
    float xn = xv * rsqrtf(total * (1.0f / D_) + EPS_) * (1.0f + w[d]);
    xs[d] = xn;
    __syncthreads();
    float c = cosb[(size_t)bs * D_ + d];
    float sn = sinb[(size_t)bs * D_ + d];
    float rot = (d < D_ / 2) ? -xs[d + D_ / 2] : xs[d - D_ / 2];
    const int b = bs / S_, s = bs % S_;
    kout[(((size_t)b * NKV_ + kh) * S_ + s) * D_ + d] = xn * c + rot * sn;
}

// ---------------- attention pass 1 ----------------
__global__ __launch_bounds__(256) void attn_stats(const float* __restrict__ q,
                                                  const float* __restrict__ k,
                                                  float* __restrict__ rowmax,
                                                  float* __restrict__ rowsum) {
    const int qt = blockIdx.x, bh = blockIdx.y;
    const int b = bh >> 4, h = bh & 15, kh = h >> 2;
    __shared__ float Qs[32][D_ + 4];
    __shared__ float Ks[32][D_ + 4];
    const int tid = threadIdx.x;
    const int q0 = qt * 32;
    {
        int rr = tid >> 3, c0 = (tid & 7) * 16;
        const float* qb = q + (((size_t)b * NH_ + h) * S_ + q0 + rr) * D_;
#pragma unroll
        for (int u = 0; u < 4; u++)
            *(float4*)&Qs[rr][c0 + u * 4] = *(const float4*)(qb + c0 + u * 4);
    }
    const float* kbase = k + (((size_t)b * NKV_ + kh) * S_) * D_;
    const int r = tid >> 3, jo = tid & 7;
    const int gi = q0 + r;
    float m = -1e30f, l = 0.0f;
    for (int kt = 0; kt <= qt; kt++) {
        __syncthreads();
        {
            int rr = tid >> 3, c0 = (tid & 7) * 16;
            const float* kb = kbase + (size_t)(kt * 32 + rr) * D_;
#pragma unroll
            for (int u = 0; u < 4; u++)
                *(float4*)&Ks[rr][c0 + u * 4] = *(const float4*)(kb + c0 + u * 4);
        }
        __syncthreads();
#pragma unroll
        for (int jj = 0; jj < 4; jj++) {
            int j = jo + jj * 8;
            int gj = kt * 32 + j;
            if (gj <= gi) {
                float acc = 0.0f;
#pragma unroll
                for (int dd = 0; dd < D_; dd += 4) {
                    float4 qv = *(const float4*)&Qs[r][dd];
                    float4 kv = *(const float4*)&Ks[j][dd];
                    acc += qv.x * kv.x + qv.y * kv.y + qv.z * kv.z + qv.w * kv.w;
                }
                float x = acc * SCALE_;
                if (x > m) { l = l * __expf(m - x) + 1.0f; m = x; }
                else       { l += __expf(x - m); }
            }
        }
    }
#pragma unroll
    for (int o = 1; o < 8; o <<= 1) {
        float m2 = __shfl_xor_sync(0xffffffffu, m, o);
        float l2 = __shfl_xor_sync(0xffffffffu, l, o);
        float mn = fmaxf(m, m2);
        l = l * __expf(m - mn) + l2 * __expf(m2 - mn);
        m = mn;
    }
    if (jo == 0) {
        rowmax[(size_t)bh * S_ + gi] = m;
        rowsum[(size_t)bh * S_ + gi] = l;
    }
}

// ---------------- attention pass 2 ----------------
__global__ __launch_bounds__(256) void attn_out(const float* __restrict__ q,
                                                const float* __restrict__ k,
                                                const float* __restrict__ v,
                                                const float* __restrict__ rowmax,
                                                const float* __restrict__ rowsum,
                                                float* __restrict__ P,
                                                float* __restrict__ octx) {
    const int qt = blockIdx.x, bh = blockIdx.y;
    const int b = bh >> 4, h = bh & 15, kh = h >> 2;
    __shared__ float Qs[32][D_ + 4];
    __shared__ float KVs[32][D_ + 4];
    __shared__ float Ps[32][36];
    const int tid = threadIdx.x;
    const int q0 = qt * 32;
    {
        int rr = tid >> 3, c0 = (tid & 7) * 16;
        const float* qb = q + (((size_t)b * NH_ + h) * S_ + q0 + rr) * D_;
#pragma unroll
        for (int u = 0; u < 4; u++)
            *(float4*)&Qs[rr][c0 + u * 4] = *(const float4*)(qb + c0 + u * 4);
    }
    const float* kbase = k + (((size_t)b * NKV_ + kh) * S_) * D_;
    const int r = tid >> 3, g = tid & 7;
    const int gi = q0 + r;
    const float m = rowmax[(size_t)bh * S_ + gi];
    const float invl = 1.0f / rowsum[(size_t)bh * S_ + gi];
    float4 o0 = {0,0,0,0}, o1 = {0,0,0,0}, o2 = {0,0,0,0}, o3 = {0,0,0,0};

    for (int kt = 0; kt <= qt; kt++) {
        __syncthreads();
        {
            int rr = tid >> 3, c0 = (tid & 7) * 16;
            const float* kb = kbase + (size_t)(kt * 32 + rr) * D_;
#pragma unroll
            for (int u = 0; u < 4; u++)
                *(float4*)&KVs[rr][c0 + u * 4] = *(const float4*)(kb + c0 + u * 4);
        }
        __syncthreads();
#pragma unroll
        for (int jj = 0; jj < 4; jj++) {
            int j = g + jj * 8;
            int gj = kt * 32 + j;
            float p = 0.0f;
            if (gj <= gi) {
                float acc = 0.0f;
#pragma unroll
                for (int dd = 0; dd < D_; dd += 4) {
                    float4 qv = *(const float4*)&Qs[r][dd];
                    float4 kv = *(const float4*)&KVs[j][dd];
                    acc += qv.x * kv.x + qv.y * kv.y + qv.z * kv.z + qv.w * kv.w;
                }
                p = __expf(acc * SCALE_ - m) * invl;
            }
            Ps[r][j] = p;
        }
        __syncthreads();
        {
            int rr = tid >> 3, c0 = (tid & 7) * 4;
            float4 pv = *(const float4*)&Ps[rr][c0];
            *(float4*)(P + ((size_t)bh * S_ + q0 + rr) * S_ + kt * 32 + c0) = pv;
        }
        {
            int rr = tid >> 3, c0 = (tid & 7) * 16;
            const float* vb = v + (((size_t)b * S_ + kt * 32 + rr) * NKV_ + kh) * D_;
#pragma unroll
            for (int u = 0; u < 4; u++)
                *(float4*)&KVs[rr][c0 + u * 4] = *(const float4*)(vb + c0 + u * 4);
        }
        __syncthreads();
#pragma unroll
        for (int j = 0; j < 32; j++) {
            float pv = Ps[r][j];
            float4 v0 = *(const float4*)&KVs[j][0 * 32 + g * 4];
            float4 v1 = *(const float4*)&KVs[j][1 * 32 + g * 4];
            float4 v2 = *(const float4*)&KVs[j][2 * 32 + g * 4];
            float4 v3 = *(const float4*)&KVs[j][3 * 32 + g * 4];
            o0.x += pv * v0.x; o0.y += pv * v0.y; o0.z += pv * v0.z; o0.w += pv * v0.w;
            o1.x += pv * v1.x; o1.y += pv * v1.y; o1.z += pv * v1.z; o1.w += pv * v1.w;
            o2.x += pv * v2.x; o2.y += pv * v2.y; o2.z += pv * v2.z; o2.w += pv * v2.w;
            o3.x += pv * v3.x; o3.y += pv * v3.y; o3.z += pv * v3.z; o3.w += pv * v3.w;
        }
    }
    float* ob = octx + (((size_t)b * S_ + gi) * NH_ + h) * D_;
    *(float4*)(ob + 0 * 32 + g * 4) = o0;
    *(float4*)(ob + 1 * 32 + g * 4) = o1;
    *(float4*)(ob + 2 * 32 + g * 4) = o2;
    *(float4*)(ob + 3 * 32 + g * 4) = o3;
}

// ---------------- zero-fill fully-masked P tiles ----------------
__global__ __launch_bounds__(128) void zero_upper(float* __restrict__ P) {
    const int row = blockIdx.x;
    const int i = row & (S_ - 1);
    const int jstart = ((i >> 5) + 1) << 5;
    float* p = P + (size_t)row * S_;
    const float4 z = {0, 0, 0, 0};
    for (int j = jstart + threadIdx.x * 4; j < S_; j += blockDim.x * 4)
        *(float4*)(p + j) = z;
}

// ---------------- gate: octx *= sigmoid(gate) ----------------
__global__ __launch_bounds__(256) void gate_mul(const float* __restrict__ qg,
                                                float* __restrict__ octx) {
    size_t i4 = (size_t)blockIdx.x * blockDim.x + threadIdx.x;
    size_t e = i4 * 4;
    int d = (int)(e % D_);
    int h = (int)((e / D_) % NH_);
    size_t bs = e / (D_ * NH_);
    const float4 gv = *(const float4*)(qg + (bs * NH_ + h) * (2 * D_) + D_ + d);
    float4 ov = *(float4*)(octx + e);
    ov.x *= 1.0f / (1.0f + expf(-gv.x));
    ov.y *= 1.0f / (1.0f + expf(-gv.y));
    ov.z *= 1.0f / (1.0f + expf(-gv.z));
    ov.w *= 1.0f / (1.0f + expf(-gv.w));
    *(float4*)(octx + e) = ov;
}

// ---------------- launch ----------------
extern "C" void kernel_launch(void* const* d_in, const int* in_sizes, int n_in,
                              void* d_out, int out_size) {
    const float* hidden = (const float*)d_in[0];
    const float* cosb   = (const float*)d_in[1];
    const float* sinb   = (const float*)d_in[2];
    const float* Wq     = (const float*)d_in[4];
    const float* Wk     = (const float*)d_in[5];
    const float* Wv     = (const float*)d_in[6];
    const float* Wo     = (const float*)d_in[7];
    const float* qnw    = (const float*)d_in[8];
    const float* knw    = (const float*)d_in[9];

    float* out = (float*)d_out;
    const size_t ao_elems = (size_t)MT_ * HID_;
    float* P = out + ao_elems;

    float *qg, *qbuf, *ktmp, *kbuf, *vbuf, *octx, *rmax, *rsum;
    __nv_bfloat16 *ahi, *alo, *wqh, *wql, *wkh, *wkl, *wvh, *wvl, *woh, *wol, *ohi, *olo;
    cudaGetSymbolAddress((void**)&qg,   g_qg);
    cudaGetSymbolAddress((void**)&qbuf, g_q);
    cudaGetSymbolAddress((void**)&ktmp, g_ktmp);
    cudaGetSymbolAddress((void**)&kbuf, g_k);
    cudaGetSymbolAddress((void**)&vbuf, g_v);
    cudaGetSymbolAddress((void**)&octx, g_octx);
    cudaGetSymbolAddress((void**)&rmax, g_rowmax);
    cudaGetSymbolAddress((void**)&rsum, g_rowsum);
    cudaGetSymbolAddress((void**)&ahi, g_ahi);
    cudaGetSymbolAddress((void**)&alo, g_alo);
    cudaGetSymbolAddress((void**)&wqh, g_wqh);
    cudaGetSymbolAddress((void**)&wql, g_wql);
    cudaGetSymbolAddress((void**)&wkh, g_wkh);
    cudaGetSymbolAddress((void**)&wkl, g_wkl);
    cudaGetSymbolAddress((void**)&wvh, g_wvh);
    cudaGetSymbolAddress((void**)&wvl, g_wvl);
    cudaGetSymbolAddress((void**)&woh, g_woh);
    cudaGetSymbolAddress((void**)&wol, g_wol);
    cudaGetSymbolAddress((void**)&ohi, g_ohi);
    cudaGetSymbolAddress((void**)&olo, g_olo);

    cudaFuncSetAttribute(gemm_bf16x3, cudaFuncAttributeMaxDynamicSharedMemorySize, GEMM_SMEM);

    // weight transpose + split, hidden split
    transpose_split<<<dim3(4096 / 32, KK_ / 32), dim3(32, 8)>>>(Wq, wqh, wql, 4096);
    transpose_split<<<dim3(512 / 32,  KK_ / 32), dim3(32, 8)>>>(Wk, wkh, wkl, 512);
    transpose_split<<<dim3(512 / 32,  KK_ / 32), dim3(32, 8)>>>(Wv, wvh, wvl, 512);
    transpose_split<<<dim3(2048 / 32, KK_ / 32), dim3(32, 8)>>>(Wo, woh, wol, 2048);
    {
        int n4 = (int)((size_t)MT_ * KK_ / 4);
        split_bf16<<<(n4 + 255) / 256, 256>>>(hidden, ahi, alo, n4);
    }

    // projections (HMMA bf16x3)
    gemm_bf16x3<<<dim3(4096 / 128, MT_ / 128), 256, GEMM_SMEM>>>(ahi, alo, wqh, wql, qg, 4096);
    gemm_bf16x3<<<dim3(512 / 128,  MT_ / 128), 256, GEMM_SMEM>>>(ahi, alo, wkh, wkl, ktmp, 512);
    gemm_bf16x3<<<dim3(512 / 128,  MT_ / 128), 256, GEMM_SMEM>>>(ahi, alo, wvh, wvl, vbuf, 512);

    // norm + rope
    norm_rope_q<<<B_ * S_ * NH_, 128>>>(qg, cosb, sinb, qnw, qbuf);
    norm_rope_k<<<B_ * S_ * NKV_, 128>>>(ktmp, cosb, sinb, knw, kbuf);

    // attention
    attn_stats<<<dim3(S_ / 32, B_ * NH_), 256>>>(qbuf, kbuf, rmax, rsum);
    attn_out<<<dim3(S_ / 32, B_ * NH_), 256>>>(qbuf, kbuf, vbuf, rmax, rsum, P, octx);
    zero_upper<<<B_ * NH_ * S_, 128>>>(P);

    // gate + output projection
    gate_mul<<<(int)(((size_t)MT_ * 2048 / 4) / 256), 256>>>(qg, octx);
    {
        int n4 = (int)((size_t)MT_ * 2048 / 4);
        split_bf16<<<(n4 + 255) / 256, 256>>>(octx, ohi, olo, n4);
    }
    gemm_bf16x3<<<dim3(2048 / 128, MT_ / 128), 256, GEMM_SMEM>>>(ohi, olo, woh, wol, out, 2048);
}

// round 4
// speedup vs baseline: 4.2773x; 3.2036x over previous
#include <cuda_runtime.h>
#include <cuda_bf16.h>
#include <cstdint>

#define B_  4
#define S_  2048
#define HID_ 2048
#define NH_ 16
#define NKV_ 4
#define D_  128
#define EPS_ 1e-6f
#define SCALE_ 0.08838834764831845f   // 128^-0.5

#define MT_  8192     // B*S rows
#define KK_  2048     // GEMM K (always HID_)

// ---------------- scratch (static __device__, allocation-free) ----------------
__device__ float g_qg  [(size_t)MT_*4096];         // (b,s,h,2D)
__device__ float g_ktmp[(size_t)MT_*512];          // (b,s,kh,d)
__device__ float g_v   [(size_t)MT_*512];          // (b,s,kh,d)
__device__ float g_octx[(size_t)MT_*2048];         // (b,s,h,d)
__device__ float g_rowmax[(size_t)B_*NH_*S_];
__device__ float g_rowsum[(size_t)B_*NH_*S_];
// bf16 hi/lo split buffers
__device__ __nv_bfloat16 g_ahi[(size_t)MT_*KK_],  g_alo[(size_t)MT_*KK_];
__device__ __nv_bfloat16 g_wqh[(size_t)4096*KK_], g_wql[(size_t)4096*KK_];
__device__ __nv_bfloat16 g_wkh[(size_t)512*KK_],  g_wkl[(size_t)512*KK_];
__device__ __nv_bfloat16 g_wvh[(size_t)512*KK_],  g_wvl[(size_t)512*KK_];
__device__ __nv_bfloat16 g_woh[(size_t)2048*KK_], g_wol[(size_t)2048*KK_];
__device__ __nv_bfloat16 g_ohi[(size_t)MT_*2048], g_olo[(size_t)MT_*2048];
// attention bf16 operands
__device__ __nv_bfloat16 g_qh[(size_t)B_*NH_*S_*D_],  g_ql[(size_t)B_*NH_*S_*D_];
__device__ __nv_bfloat16 g_k2h[(size_t)B_*NKV_*S_*D_], g_k2l[(size_t)B_*NKV_*S_*D_];
__device__ __nv_bfloat16 g_vth[(size_t)B_*NKV_*D_*S_], g_vtl[(size_t)B_*NKV_*D_*S_];

// ================= PTX helpers (family-target-safe: sm_80+ features only) =====
__device__ __forceinline__ uint32_t smem_u32(const void* p) {
    uint32_t a;
    asm("{ .reg .u64 t; cvta.to.shared.u64 t, %1; cvt.u32.u64 %0, t; }" : "=r"(a) : "l"(p));
    return a;
}
__device__ __forceinline__ void cp16(uint32_t s, const void* g) {
    asm volatile("cp.async.cg.shared.global [%0], [%1], 16;" :: "r"(s), "l"(g));
}
__device__ __forceinline__ void ldm4(uint32_t* r, uint32_t addr) {
    asm volatile("ldmatrix.sync.aligned.m8n8.x4.shared.b16 {%0,%1,%2,%3}, [%4];"
                 : "=r"(r[0]), "=r"(r[1]), "=r"(r[2]), "=r"(r[3]) : "r"(addr));
}
__device__ __forceinline__ void mma_bf16(float* c, const uint32_t* a, const uint32_t* b) {
    asm volatile("mma.sync.aligned.m16n8k16.row.col.f32.bf16.bf16.f32 "
                 "{%0,%1,%2,%3}, {%4,%5,%6,%7}, {%8,%9}, {%0,%1,%2,%3};"
                 : "+f"(c[0]), "+f"(c[1]), "+f"(c[2]), "+f"(c[3])
                 : "r"(a[0]), "r"(a[1]), "r"(a[2]), "r"(a[3]), "r"(b[0]), "r"(b[1]));
}
// swizzled smem offsets: 128B rows (8 chunks) and 256B rows (16 chunks)
__device__ __forceinline__ uint32_t phys(int r, int c) {
    return (uint32_t)(r * 128 + ((c ^ (r & 7)) << 4));
}
__device__ __forceinline__ uint32_t phys256(int r, int c) {
    return (uint32_t)(r * 256 + (((c & 7) ^ (r & 7)) << 4) + ((c & 8) << 4));
}
__device__ __forceinline__ void split_pack(float a, float b, uint32_t& hi, uint32_t& lo) {
    __nv_bfloat16 ha = __float2bfloat16(a), hb = __float2bfloat16(b);
    __nv_bfloat16 la = __float2bfloat16(a - __bfloat162float(ha));
    __nv_bfloat16 lb = __float2bfloat16(b - __bfloat162float(hb));
    __nv_bfloat162 H(ha, hb), L(la, lb);
    hi = *(uint32_t*)&H;
    lo = *(uint32_t*)&L;
}

#define STG_BYTES 65536          // per pipeline stage: Ahi|Alo|Bhi|Blo, 16KB each
#define GEMM_SMEM (2 * STG_BYTES)

// ======= HMMA bf16x3-split GEMM: C[M,N] = A[M,K] * Bt[N,K]^T (M=8192,K=2048) ====
__global__ __launch_bounds__(256, 1) void gemm_bf16x3(
    const __nv_bfloat16* __restrict__ Ahi, const __nv_bfloat16* __restrict__ Alo,
    const __nv_bfloat16* __restrict__ Bhi, const __nv_bfloat16* __restrict__ Blo,
    float* __restrict__ C, int N) {
    extern __shared__ char smem[];
    const uint32_t sb = smem_u32(smem);
    const int tid = threadIdx.x, wid = tid >> 5, lane = tid & 31;
    const int m0 = blockIdx.y * 128, n0 = blockIdx.x * 128;
    const int NKI = KK_ / 64;    // 32 iters

    const __nv_bfloat16* ah = Ahi + (size_t)m0 * KK_;
    const __nv_bfloat16* al = Alo + (size_t)m0 * KK_;
    const __nv_bfloat16* bh = Bhi + (size_t)n0 * KK_;
    const __nv_bfloat16* bl = Blo + (size_t)n0 * KK_;

    auto load_stage = [&](int st, int it) {
        const uint32_t base = sb + st * STG_BYTES;
        const int k0 = it * 64;
        for (int q = tid; q < 4096; q += 256) {
            int reg = q >> 10, qq = q & 1023;
            int r = qq >> 3, c = qq & 7;
            const __nv_bfloat16* src;
            switch (reg) {
                case 0: src = ah; break;
                case 1: src = al; break;
                case 2: src = bh; break;
                default: src = bl; break;
            }
            cp16(base + reg * 16384 + phys(r, c), src + (size_t)r * KK_ + k0 + c * 8);
        }
        asm volatile("cp.async.commit_group;" ::: "memory");
    };

    load_stage(0, 0);
    load_stage(1, 1);

    const int wm = (wid & 3) * 32;
    const int wn = (wid >> 2) * 64;
    float acc[2][8][4];
#pragma unroll
    for (int i = 0; i < 2; i++)
#pragma unroll
        for (int j = 0; j < 8; j++)
#pragma unroll
            for (int q = 0; q < 4; q++) acc[i][j][q] = 0.0f;

    const int fr = (lane & 7) + ((lane >> 3) & 1) * 8;
    const int fc = lane >> 4;

    for (int i = 0; i < NKI; i++) {
        const int st = i & 1;
        if (i == NKI - 1) asm volatile("cp.async.wait_group 0;" ::: "memory");
        else              asm volatile("cp.async.wait_group 1;" ::: "memory");
        __syncthreads();

        const uint32_t bA = sb + st * STG_BYTES;
        const uint32_t bAl = bA + 16384, bB = bA + 32768, bBl = bA + 49152;
#pragma unroll
        for (int s = 0; s < 4; s++) {
            uint32_t ahf[2][4], alf[2][4], bhf[8][2], blf[8][2];
#pragma unroll
            for (int mi = 0; mi < 2; mi++) {
                int r = wm + mi * 16 + fr;
                uint32_t off = phys(r, s * 2 + fc);
                ldm4(ahf[mi], bA + off);
                ldm4(alf[mi], bAl + off);
            }
#pragma unroll
            for (int ng = 0; ng < 4; ng++) {
                int r = wn + ng * 16 + fr;
                uint32_t off = phys(r, s * 2 + fc);
                uint32_t t[4];
                ldm4(t, bB + off);
                bhf[ng * 2][0] = t[0]; bhf[ng * 2][1] = t[2];
                bhf[ng * 2 + 1][0] = t[1]; bhf[ng * 2 + 1][1] = t[3];
                ldm4(t, bBl + off);
                blf[ng * 2][0] = t[0]; blf[ng * 2][1] = t[2];
                blf[ng * 2 + 1][0] = t[1]; blf[ng * 2 + 1][1] = t[3];
            }
#pragma unroll
            for (int mi = 0; mi < 2; mi++)
#pragma unroll
                for (int n = 0; n < 8; n++) {
                    mma_bf16(acc[mi][n], ahf[mi], bhf[n]);
                    mma_bf16(acc[mi][n], ahf[mi], blf[n]);
                    mma_bf16(acc[mi][n], alf[mi], bhf[n]);
                }
        }
        __syncthreads();
        if (i + 2 < NKI) load_stage(st, i + 2);
    }

#pragma unroll
    for (int mi = 0; mi < 2; mi++) {
        int r0 = m0 + wm + mi * 16 + (lane >> 2);
#pragma unroll
        for (int n = 0; n < 8; n++) {
            int col = n0 + wn + n * 8 + (lane & 3) * 2;
            *(float2*)(C + (size_t)r0 * N + col)       = make_float2(acc[mi][n][0], acc[mi][n][1]);
            *(float2*)(C + (size_t)(r0 + 8) * N + col) = make_float2(acc[mi][n][2], acc[mi][n][3]);
        }
    }
}

// ============ fp32 -> bf16 hi/lo split ============
__global__ __launch_bounds__(256) void split_bf16(const float* __restrict__ x,
                                                  __nv_bfloat16* __restrict__ hi,
                                                  __nv_bfloat16* __restrict__ lo,
                                                  int n4) {
    int i = blockIdx.x * 256 + threadIdx.x;
    if (i >= n4) return;
    float4 v = ((const float4*)x)[i];
    __nv_bfloat16 h0 = __float2bfloat16(v.x), h1 = __float2bfloat16(v.y);
    __nv_bfloat16 h2 = __float2bfloat16(v.z), h3 = __float2bfloat16(v.w);
    __nv_bfloat16 l0 = __float2bfloat16(v.x - __bfloat162float(h0));
    __nv_bfloat16 l1 = __float2bfloat16(v.y - __bfloat162float(h1));
    __nv_bfloat16 l2 = __float2bfloat16(v.z - __bfloat162float(h2));
    __nv_bfloat16 l3 = __float2bfloat16(v.w - __bfloat162float(h3));
    ((__nv_bfloat162*)hi)[2 * i]     = __nv_bfloat162(h0, h1);
    ((__nv_bfloat162*)hi)[2 * i + 1] = __nv_bfloat162(h2, h3);
    ((__nv_bfloat162*)lo)[2 * i]     = __nv_bfloat162(l0, l1);
    ((__nv_bfloat162*)lo)[2 * i + 1] = __nv_bfloat162(l2, l3);
}

// ============ W[K,N] fp32 -> Wt hi/lo bf16 [N,K] ============
__global__ __launch_bounds__(256) void transpose_split(const float* __restrict__ W,
                                                       __nv_bfloat16* __restrict__ thi,
                                                       __nv_bfloat16* __restrict__ tlo,
                                                       int N) {
    __shared__ float t[32][33];
    const int n0 = blockIdx.x * 32, k0 = blockIdx.y * 32;
    const int tx = threadIdx.x, ty = threadIdx.y;
    for (int i = ty; i < 32; i += 8)
        t[i][tx] = W[(size_t)(k0 + i) * N + n0 + tx];
    __syncthreads();
    for (int i = ty; i < 32; i += 8) {
        float v = t[tx][i];
        __nv_bfloat16 h = __float2bfloat16(v);
        __nv_bfloat16 l = __float2bfloat16(v - __bfloat162float(h));
        thi[(size_t)(n0 + i) * KK_ + k0 + tx] = h;
        tlo[(size_t)(n0 + i) * KK_ + k0 + tx] = l;
    }
}

// ============ V fp32 (b,s,kh,d) -> V^T hi/lo bf16 (b,kh,d,s) ============
__global__ __launch_bounds__(256) void v_split_trans(const float* __restrict__ v,
                                                     __nv_bfloat16* __restrict__ vth,
                                                     __nv_bfloat16* __restrict__ vtl) {
    __shared__ float t[32][33];
    const int bk = blockIdx.z;
    const int b = bk >> 2, kv = bk & 3;
    const int s0 = blockIdx.x * 32, d0 = blockIdx.y * 32;
    const int tx = threadIdx.x, ty = threadIdx.y;
    for (int i = ty; i < 32; i += 8)
        t[i][tx] = v[((size_t)(b * S_ + s0 + i) * NKV_ + kv) * D_ + d0 + tx];
    __syncthreads();
    for (int i = ty; i < 32; i += 8) {
        float val = t[tx][i];
        __nv_bfloat16 h = __float2bfloat16(val);
        __nv_bfloat16 l = __float2bfloat16(val - __bfloat162float(h));
        size_t o = ((size_t)(b * NKV_ + kv) * D_ + d0 + i) * S_ + s0 + tx;
        vth[o] = h;
        vtl[o] = l;
    }
}

// ---------------- RMSNorm + RoPE -> bf16 hi/lo ----------------
__global__ __launch_bounds__(128) void norm_rope_q_bf(const float* __restrict__ qg,
                                                      const float* __restrict__ cosb,
                                                      const float* __restrict__ sinb,
                                                      const float* __restrict__ w,
                                                      __nv_bfloat16* __restrict__ qh,
                                                      __nv_bfloat16* __restrict__ ql) {
    const int idx = blockIdx.x;
    const int h = idx % NH_;
    const int bs = idx / NH_;
    const int d = threadIdx.x;
    const float* x = qg + ((size_t)bs * NH_ + h) * (2 * D_);
    float xv = x[d];
    float sq = xv * xv;
#pragma unroll
    for (int o = 16; o > 0; o >>= 1) sq += __shfl_xor_sync(0xffffffffu, sq, o);
    __shared__ float wsum[4];
    __shared__ float xs[D_];
    if ((d & 31) == 0) wsum[d >> 5] = sq;
    __syncthreads();
    float total = wsum[0] + wsum[1] + wsum[2] + wsum[3];
    float xn = xv * rsqrtf(total * (1.0f / D_) + EPS_) * (1.0f + w[d]);
    xs[d] = xn;
    __syncthreads();
    float c = cosb[(size_t)bs * D_ + d];
    float sn = sinb[(size_t)bs * D_ + d];
    float rot = (d < D_ / 2) ? -xs[d + D_ / 2] : xs[d - D_ / 2];
    float val = xn * c + rot * sn;
    const int b = bs / S_, s = bs % S_;
    size_t o = (((size_t)b * NH_ + h) * S_ + s) * D_ + d;
    __nv_bfloat16 hi = __float2bfloat16(val);
    qh[o] = hi;
    ql[o] = __float2bfloat16(val - __bfloat162float(hi));
}

__global__ __launch_bounds__(128) void norm_rope_k_bf(const float* __restrict__ kin,
                                                      const float* __restrict__ cosb,
                                                      const float* __restrict__ sinb,
                                                      const float* __restrict__ w,
                                                      __nv_bfloat16* __restrict__ kh,
                                                      __nv_bfloat16* __restrict__ kl) {
    const int idx = blockIdx.x;
    const int kv = idx % NKV_;
    const int bs = idx / NKV_;
    const int d = threadIdx.x;
    const float* x = kin + ((size_t)bs * NKV_ + kv) * D_;
    float xv = x[d];
    float sq = xv * xv;
#pragma unroll
    for (int o = 16; o > 0; o >>= 1) sq += __shfl_xor_sync(0xffffffffu, sq, o);
    __shared__ float wsum[4];
    __shared__ float xs[D_];
    if ((d & 31) == 0) wsum[d >> 5] = sq;
    __syncthreads();
    float total = wsum[0] + wsum[1] + wsum[2] + wsum[3];
    float xn = xv * rsqrtf(total * (1.0f / D_) + EPS_) * (1.0f + w[d]);
    xs[d] = xn;
    __syncthreads();
    float c = cosb[(size_t)bs * D_ + d];
    float sn = sinb[(size_t)bs * D_ + d];
    float rot = (d < D_ / 2) ? -xs[d + D_ / 2] : xs[d - D_ / 2];
    float val = xn * c + rot * sn;
    const int b = bs / S_, s = bs % S_;
    size_t o = (((size_t)b * NKV_ + kv) * S_ + s) * D_ + d;
    __nv_bfloat16 hi = __float2bfloat16(val);
    kh[o] = hi;
    kl[o] = __float2bfloat16(val - __bfloat162float(hi));
}

// ======================= attention pass 1: HMMA stats =======================
// grid (S/128, B*NH). smem: Q hi/lo 64KB + 2 stages of K hi/lo (32KB each)
#define P1_SMEM 131072
__global__ __launch_bounds__(256, 1) void attn_stats_mma(
    const __nv_bfloat16* __restrict__ qh, const __nv_bfloat16* __restrict__ ql,
    const __nv_bfloat16* __restrict__ khb, const __nv_bfloat16* __restrict__ klb,
    float* __restrict__ rowmax, float* __restrict__ rowsum) {
    extern __shared__ char smem[];
    const uint32_t sb = smem_u32(smem);
    const int tid = threadIdx.x, wid = tid >> 5, lane = tid & 31;
    const int qt = blockIdx.x, bh = blockIdx.y;
    const int b = bh >> 4, h = bh & 15, kv = h >> 2;
    const int q0 = qt * 128;
    const int nk = 2 * qt + 2;
    const __nv_bfloat16* qhp = qh + ((size_t)(b * NH_ + h) * S_ + q0) * D_;
    const __nv_bfloat16* qlp = ql + ((size_t)(b * NH_ + h) * S_ + q0) * D_;
    const __nv_bfloat16* khp = khb + (size_t)(b * NKV_ + kv) * S_ * D_;
    const __nv_bfloat16* klp = klb + (size_t)(b * NKV_ + kv) * S_ * D_;

    for (int q = tid; q < 2048; q += 256) {
        int r = q >> 4, c = q & 15;
        uint32_t off = phys256(r, c);
        cp16(sb + off, qhp + (size_t)r * D_ + c * 8);
        cp16(sb + 32768 + off, qlp + (size_t)r * D_ + c * 8);
    }
    auto load_k = [&](int st, int kt) {
        uint32_t base = sb + 65536 + st * 32768;
        const __nv_bfloat16* sh = khp + (size_t)kt * 64 * D_;
        const __nv_bfloat16* sl = klp + (size_t)kt * 64 * D_;
        for (int q = tid; q < 1024; q += 256) {
            int r = q >> 4, c = q & 15;
            uint32_t off = phys256(r, c);
            cp16(base + off, sh + (size_t)r * D_ + c * 8);
            cp16(base + 16384 + off, sl + (size_t)r * D_ + c * 8);
        }
    };
    load_k(0, 0);
    asm volatile("cp.async.commit_group;" ::: "memory");
    load_k(1, 1);
    asm volatile("cp.async.commit_group;" ::: "memory");

    const int wm = (wid & 3) * 32, wn = (wid >> 2) * 32;
    const int fr = (lane & 7) + ((lane >> 3) & 1) * 8;
    const int fc = lane >> 4;
    float m[4] = {-1e30f, -1e30f, -1e30f, -1e30f};
    float l[4] = {0.0f, 0.0f, 0.0f, 0.0f};

    for (int kt = 0; kt < nk; kt++) {
        if (kt == nk - 1) asm volatile("cp.async.wait_group 0;" ::: "memory");
        else              asm volatile("cp.async.wait_group 1;" ::: "memory");
        __syncthreads();
        const uint32_t bK = sb + 65536 + (kt & 1) * 32768;
        const uint32_t bKl = bK + 16384;

        float acc[2][4][4];
#pragma unroll
        for (int i = 0; i < 2; i++)
#pragma unroll
            for (int j = 0; j < 4; j++)
#pragma unroll
                for (int q = 0; q < 4; q++) acc[i][j][q] = 0.0f;

#pragma unroll
        for (int ks = 0; ks < 8; ks++) {
            uint32_t ahf[2][4], alf[2][4], bhf[4][2], blf[4][2];
#pragma unroll
            for (int mi = 0; mi < 2; mi++) {
                uint32_t off = phys256(wm + mi * 16 + fr, ks * 2 + fc);
                ldm4(ahf[mi], sb + off);
                ldm4(alf[mi], sb + 32768 + off);
            }
#pragma unroll
            for (int ng = 0; ng < 2; ng++) {
                uint32_t off = phys256(wn + ng * 16 + fr, ks * 2 + fc);
                uint32_t t[4];
                ldm4(t, bK + off);
                bhf[ng * 2][0] = t[0]; bhf[ng * 2][1] = t[2];
                bhf[ng * 2 + 1][0] = t[1]; bhf[ng * 2 + 1][1] = t[3];
                ldm4(t, bKl + off);
                blf[ng * 2][0] = t[0]; blf[ng * 2][1] = t[2];
                blf[ng * 2 + 1][0] = t[1]; blf[ng * 2 + 1][1] = t[3];
            }
#pragma unroll
            for (int mi = 0; mi < 2; mi++)
#pragma unroll
                for (int n = 0; n < 4; n++) {
                    mma_bf16(acc[mi][n], ahf[mi], bhf[n]);
                    mma_bf16(acc[mi][n], ahf[mi], blf[n]);
                    mma_bf16(acc[mi][n], alf[mi], bhf[n]);
                }
        }

        const bool full = (kt * 64 + 63 <= q0);
#pragma unroll
        for (int mi = 0; mi < 2; mi++)
#pragma unroll
            for (int half = 0; half < 2; half++) {
                const int slot = mi * 2 + half;
                const int gi = q0 + wm + mi * 16 + (lane >> 2) + half * 8;
                float mx = m[slot];
                if (full) {
#pragma unroll
                    for (int n = 0; n < 4; n++) {
                        mx = fmaxf(mx, acc[mi][n][half * 2] * SCALE_);
                        mx = fmaxf(mx, acc[mi][n][half * 2 + 1] * SCALE_);
                    }
                    float ll = l[slot] * __expf(m[slot] - mx);
#pragma unroll
                    for (int n = 0; n < 4; n++) {
                        ll += __expf(acc[mi][n][half * 2] * SCALE_ - mx);
                        ll += __expf(acc[mi][n][half * 2 + 1] * SCALE_ - mx);
                    }
                    m[slot] = mx; l[slot] = ll;
                } else {
#pragma unroll
                    for (int n = 0; n < 4; n++)
#pragma unroll
                        for (int e = 0; e < 2; e++) {
                            int gj = kt * 64 + wn + n * 8 + (lane & 3) * 2 + e;
                            if (gj <= gi) mx = fmaxf(mx, acc[mi][n][half * 2 + e] * SCALE_);
                        }
                    float ll = l[slot] * __expf(m[slot] - mx);
#pragma unroll
                    for (int n = 0; n < 4; n++)
#pragma unroll
                        for (int e = 0; e < 2; e++) {
                            int gj = kt * 64 + wn + n * 8 + (lane & 3) * 2 + e;
                            if (gj <= gi) ll += __expf(acc[mi][n][half * 2 + e] * SCALE_ - mx);
                        }
                    m[slot] = mx; l[slot] = ll;
                }
            }
        __syncthreads();
        if (kt + 2 < nk) {
            load_k(kt & 1, kt + 2);
            asm volatile("cp.async.commit_group;" ::: "memory");
        }
    }

    // reduce across 4 lanes sharing a row
#pragma unroll
    for (int o = 1; o < 4; o <<= 1)
#pragma unroll
        for (int slot = 0; slot < 4; slot++) {
            float m2 = __shfl_xor_sync(0xffffffffu, m[slot], o);
            float l2 = __shfl_xor_sync(0xffffffffu, l[slot], o);
            float mn = fmaxf(m[slot], m2);
            l[slot] = l[slot] * __expf(m[slot] - mn) + l2 * __expf(m2 - mn);
            m[slot] = mn;
        }
    __syncthreads();
    float* smf = (float*)smem;
    if ((lane & 3) == 0) {
#pragma unroll
        for (int slot = 0; slot < 4; slot++) {
            int rl = wm + (slot >> 1) * 16 + (lane >> 2) + (slot & 1) * 8;
            smf[(wid >> 2) * 128 + rl] = m[slot];
            smf[256 + (wid >> 2) * 128 + rl] = l[slot];
        }
    }
    __syncthreads();
    if (tid < 128) {
        float m0 = smf[tid], m1 = smf[128 + tid];
        float l0 = smf[256 + tid], l1 = smf[384 + tid];
        float mn = fmaxf(m0, m1);
        float ll = l0 * __expf(m0 - mn) + l1 * __expf(m1 - mn);
        rowmax[(size_t)bh * S_ + q0 + tid] = mn;
        rowsum[(size_t)bh * S_ + q0 + tid] = ll;
    }
}

// ============== attention pass 2: HMMA P-write + PV ==============
// smem: Q 64KB + 2 stages of (Khi,Klo,Vhi,Vlo) 64KB each = 192KB
#define P2_SMEM 196608
__global__ __launch_bounds__(256, 1) void attn_pv_mma(
    const __nv_bfloat16* __restrict__ qh, const __nv_bfloat16* __restrict__ ql,
    const __nv_bfloat16* __restrict__ khb, const __nv_bfloat16* __restrict__ klb,
    const __nv_bfloat16* __restrict__ vth, const __nv_bfloat16* __restrict__ vtl,
    const float* __restrict__ rowmax, const float* __restrict__ rowsum,
    float* __restrict__ P, float* __restrict__ octx) {
    extern __shared__ char smem[];
    const uint32_t sb = smem_u32(smem);
    const int tid = threadIdx.x, wid = tid >> 5, lane = tid & 31;
    const int qt = blockIdx.x, bh = blockIdx.y;
    const int b = bh >> 4, h = bh & 15, kv = h >> 2;
    const int q0 = qt * 128;
    const int nk = 2 * qt + 2;
    const __nv_bfloat16* qhp = qh + ((size_t)(b * NH_ + h) * S_ + q0) * D_;
    const __nv_bfloat16* qlp = ql + ((size_t)(b * NH_ + h) * S_ + q0) * D_;
    const __nv_bfloat16* khp = khb + (size_t)(b * NKV_ + kv) * S_ * D_;
    const __nv_bfloat16* klp = klb + (size_t)(b * NKV_ + kv) * S_ * D_;
    const __nv_bfloat16* vhp = vth + (size_t)(b * NKV_ + kv) * D_ * S_;
    const __nv_bfloat16* vlp = vtl + (size_t)(b * NKV_ + kv) * D_ * S_;

    for (int q = tid; q < 2048; q += 256) {
        int r = q >> 4, c = q & 15;
        uint32_t off = phys256(r, c);
        cp16(sb + off, qhp + (size_t)r * D_ + c * 8);
        cp16(sb + 32768 + off, qlp + (size_t)r * D_ + c * 8);
    }
    auto load_stage = [&](int st, int kt) {
        uint32_t base = sb + 65536 + st * 65536;
        const __nv_bfloat16* sh = khp + (size_t)kt * 64 * D_;
        const __nv_bfloat16* sl = klp + (size_t)kt * 64 * D_;
        for (int q = tid; q < 1024; q += 256) {
            int r = q >> 4, c = q & 15;
            uint32_t off = phys256(r, c);
            cp16(base + off, sh + (size_t)r * D_ + c * 8);
            cp16(base + 16384 + off, sl + (size_t)r * D_ + c * 8);
        }
        for (int q = tid; q < 1024; q += 256) {
            int r = q >> 3, c = q & 7;
            uint32_t off = phys(r, c);
            cp16(base + 32768 + off, vhp + (size_t)r * S_ + kt * 64 + c * 8);
            cp16(base + 49152 + off, vlp + (size_t)r * S_ + kt * 64 + c * 8);
        }
    };
    load_stage(0, 0);
    asm volatile("cp.async.commit_group;" ::: "memory");
    load_stage(1, 1);
    asm volatile("cp.async.commit_group;" ::: "memory");

    const int wm = (wid & 3) * 32, wn = (wid >> 2) * 32;
    const int fr = (lane & 7) + ((lane >> 3) & 1) * 8;
    const int fc = lane >> 4;

    float mrow[4], il[4];
#pragma unroll
    for (int slot = 0; slot < 4; slot++) {
        int gi = q0 + wm + (slot >> 1) * 16 + (lane >> 2) + (slot & 1) * 8;
        mrow[slot] = rowmax[(size_t)bh * S_ + gi];
        il[slot] = 1.0f / rowsum[(size_t)bh * S_ + gi];
    }

    float pv[2][16][4];
#pragma unroll
    for (int mi = 0; mi < 2; mi++)
#pragma unroll
        for (int n = 0; n < 16; n++)
#pragma unroll
            for (int q = 0; q < 4; q++) pv[mi][n][q] = 0.0f;

    for (int kt = 0; kt < nk; kt++) {
        if (kt == nk - 1) asm volatile("cp.async.wait_group 0;" ::: "memory");
        else              asm volatile("cp.async.wait_group 1;" ::: "memory");
        __syncthreads();
        const uint32_t stg = sb + 65536 + (kt & 1) * 65536;
        const uint32_t bK = stg, bKl = stg + 16384, bV = stg + 32768, bVl = stg + 49152;

        float acc[2][4][4];
#pragma unroll
        for (int i = 0; i < 2; i++)
#pragma unroll
            for (int j = 0; j < 4; j++)
#pragma unroll
                for (int q = 0; q < 4; q++) acc[i][j][q] = 0.0f;

#pragma unroll
        for (int ks = 0; ks < 8; ks++) {
            uint32_t ahf[2][4], alf[2][4], bhf[4][2], blf[4][2];
#pragma unroll
            for (int mi = 0; mi < 2; mi++) {
                uint32_t off = phys256(wm + mi * 16 + fr, ks * 2 + fc);
                ldm4(ahf[mi], sb + off);
                ldm4(alf[mi], sb + 32768 + off);
            }
#pragma unroll
            for (int ng = 0; ng < 2; ng++) {
                uint32_t off = phys256(wn + ng * 16 + fr, ks * 2 + fc);
                uint32_t t[4];
                ldm4(t, bK + off);
                bhf[ng * 2][0] = t[0]; bhf[ng * 2][1] = t[2];
                bhf[ng * 2 + 1][0] = t[1]; bhf[ng * 2 + 1][1] = t[3];
                ldm4(t, bKl + off);
                blf[ng * 2][0] = t[0]; blf[ng * 2][1] = t[2];
                blf[ng * 2 + 1][0] = t[1]; blf[ng * 2 + 1][1] = t[3];
            }
#pragma unroll
            for (int mi = 0; mi < 2; mi++)
#pragma unroll
                for (int n = 0; n < 4; n++) {
                    mma_bf16(acc[mi][n], ahf[mi], bhf[n]);
                    mma_bf16(acc[mi][n], ahf[mi], blf[n]);
                    mma_bf16(acc[mi][n], alf[mi], bhf[n]);
                }
        }

        // P = softmax prob (masked -> 0), write to gmem
        const bool full = (kt * 64 + 63 <= q0);
#pragma unroll
        for (int mi = 0; mi < 2; mi++)
#pragma unroll
            for (int n = 0; n < 4; n++)
#pragma unroll
                for (int e = 0; e < 4; e++) {
                    const int slot = mi * 2 + (e >> 1);
                    float x = acc[mi][n][e] * SCALE_;
                    float p = __expf(x - mrow[slot]) * il[slot];
                    if (!full) {
                        int gi = q0 + wm + mi * 16 + (lane >> 2) + (e >> 1) * 8;
                        int gj = kt * 64 + wn + n * 8 + (lane & 3) * 2 + (e & 1);
                        if (gj > gi) p = 0.0f;
                    }
                    acc[mi][n][e] = p;
                }
#pragma unroll
        for (int mi = 0; mi < 2; mi++) {
            int r0 = q0 + wm + mi * 16 + (lane >> 2);
#pragma unroll
            for (int n = 0; n < 4; n++) {
                int col = kt * 64 + wn + n * 8 + (lane & 3) * 2;
                *(float2*)(P + ((size_t)bh * S_ + r0) * S_ + col) =
                    make_float2(acc[mi][n][0], acc[mi][n][1]);
                *(float2*)(P + ((size_t)bh * S_ + r0 + 8) * S_ + col) =
                    make_float2(acc[mi][n][2], acc[mi][n][3]);
            }
        }

        // PV: P (as A frags, hi/lo) x V^T (B frags, hi/lo)
#pragma unroll
        for (int ksl = 0; ksl < 2; ksl++) {
            uint32_t pah[2][4], pal[2][4];
#pragma unroll
            for (int mi = 0; mi < 2; mi++) {
                const int n0 = ksl * 2, n1 = ksl * 2 + 1;
                split_pack(acc[mi][n0][0], acc[mi][n0][1], pah[mi][0], pal[mi][0]);
                split_pack(acc[mi][n0][2], acc[mi][n0][3], pah[mi][1], pal[mi][1]);
                split_pack(acc[mi][n1][0], acc[mi][n1][1], pah[mi][2], pal[mi][2]);
                split_pack(acc[mi][n1][2], acc[mi][n1][3], pah[mi][3], pal[mi][3]);
            }
            const int cc = (wn >> 3) + ksl * 2;
#pragma unroll
            for (int dg = 0; dg < 8; dg++) {
                uint32_t t[4], bh2[2][2], bl2[2][2];
                uint32_t off = phys(dg * 16 + fr, cc + fc);
                ldm4(t, bV + off);
                bh2[0][0] = t[0]; bh2[0][1] = t[2];
                bh2[1][0] = t[1]; bh2[1][1] = t[3];
                ldm4(t, bVl + off);
                bl2[0][0] = t[0]; bl2[0][1] = t[2];
                bl2[1][0] = t[1]; bl2[1][1] = t[3];
#pragma unroll
                for (int mi = 0; mi < 2; mi++)
#pragma unroll
                    for (int sub = 0; sub < 2; sub++) {
                        const int nf = dg * 2 + sub;
                        mma_bf16(pv[mi][nf], pah[mi], bh2[sub]);
                        mma_bf16(pv[mi][nf], pah[mi], bl2[sub]);
                        mma_bf16(pv[mi][nf], pal[mi], bh2[sub]);
                    }
            }
        }
        __syncthreads();
        if (kt + 2 < nk) {
            load_stage(kt & 1, kt + 2);
            asm volatile("cp.async.commit_group;" ::: "memory");
        }
    }

    // combine the two col-warp groups and store octx
    __syncthreads();
    float* ob = (float*)smem;          // 128 rows x pitch 136 floats (~70KB)
    if (wn == 32) {
#pragma unroll
        for (int mi = 0; mi < 2; mi++) {
            int r0 = wm + mi * 16 + (lane >> 2);
#pragma unroll
            for (int nf = 0; nf < 16; nf++) {
                int d = nf * 8 + (lane & 3) * 2;
                *(float2*)&ob[(size_t)r0 * 136 + d]       = make_float2(pv[mi][nf][0], pv[mi][nf][1]);
                *(float2*)&ob[(size_t)(r0 + 8) * 136 + d] = make_float2(pv[mi][nf][2], pv[mi][nf][3]);
            }
        }
    }
    __syncthreads();
    if (wn == 0) {
#pragma unroll
        for (int mi = 0; mi < 2; mi++) {
            int r0 = wm + mi * 16 + (lane >> 2);
#pragma unroll
            for (int nf = 0; nf < 16; nf++) {
                int d = nf * 8 + (lane & 3) * 2;
                float2 a0 = *(float2*)&ob[(size_t)r0 * 136 + d];
                float2 a1 = *(float2*)&ob[(size_t)(r0 + 8) * 136 + d];
                float* o0 = octx + ((size_t)(b * S_ + q0 + r0) * NH_ + h) * D_ + d;
                float* o1 = octx + ((size_t)(b * S_ + q0 + r0 + 8) * NH_ + h) * D_ + d;
                *(float2*)o0 = make_float2(pv[mi][nf][0] + a0.x, pv[mi][nf][1] + a0.y);
                *(float2*)o1 = make_float2(pv[mi][nf][2] + a1.x, pv[mi][nf][3] + a1.y);
            }
        }
    }
}

// ---------------- zero-fill fully-masked P region (cols >= next 128-tile) ------
__global__ __launch_bounds__(128) void zero_upper(float* __restrict__ P) {
    const int row = blockIdx.x;
    const int i = row & (S_ - 1);
    const int jstart = ((i >> 7) + 1) << 7;
    float* p = P + (size_t)row * S_;
    const float4 z = {0, 0, 0, 0};
    for (int j = jstart + threadIdx.x * 4; j < S_; j += blockDim.x * 4)
        *(float4*)(p + j) = z;
}

// ---------------- gate: octx *= sigmoid(gate) ----------------
__global__ __launch_bounds__(256) void gate_mul(const float* __restrict__ qg,
                                                float* __restrict__ octx) {
    size_t i4 = (size_t)blockIdx.x * blockDim.x + threadIdx.x;
    size_t e = i4 * 4;
    int d = (int)(e % D_);
    int h = (int)((e / D_) % NH_);
    size_t bs = e / (D_ * NH_);
    const float4 gv = *(const float4*)(qg + (bs * NH_ + h) * (2 * D_) + D_ + d);
    float4 ov = *(float4*)(octx + e);
    ov.x *= 1.0f / (1.0f + expf(-gv.x));
    ov.y *= 1.0f / (1.0f + expf(-gv.y));
    ov.z *= 1.0f / (1.0f + expf(-gv.z));
    ov.w *= 1.0f / (1.0f + expf(-gv.w));
    *(float4*)(octx + e) = ov;
}

// ---------------- launch ----------------
extern "C" void kernel_launch(void* const* d_in, const int* in_sizes, int n_in,
                              void* d_out, int out_size) {
    const float* hidden = (const float*)d_in[0];
    const float* cosb   = (const float*)d_in[1];
    const float* sinb   = (const float*)d_in[2];
    const float* Wq     = (const float*)d_in[4];
    const float* Wk     = (const float*)d_in[5];
    const float* Wv     = (const float*)d_in[6];
    const float* Wo     = (const float*)d_in[7];
    const float* qnw    = (const float*)d_in[8];
    const float* knw    = (const float*)d_in[9];

    float* out = (float*)d_out;
    const size_t ao_elems = (size_t)MT_ * HID_;
    float* P = out + ao_elems;

    float *qg, *ktmp, *vbuf, *octx, *rmax, *rsum;
    __nv_bfloat16 *ahi, *alo, *wqh, *wql, *wkh, *wkl, *wvh, *wvl, *woh, *wol, *ohi, *olo;
    __nv_bfloat16 *qhv, *qlv, *k2h, *k2l, *vth, *vtl;
    cudaGetSymbolAddress((void**)&qg,   g_qg);
    cudaGetSymbolAddress((void**)&ktmp, g_ktmp);
    cudaGetSymbolAddress((void**)&vbuf, g_v);
    cudaGetSymbolAddress((void**)&octx, g_octx);
    cudaGetSymbolAddress((void**)&rmax, g_rowmax);
    cudaGetSymbolAddress((void**)&rsum, g_rowsum);
    cudaGetSymbolAddress((void**)&ahi, g_ahi);
    cudaGetSymbolAddress((void**)&alo, g_alo);
    cudaGetSymbolAddress((void**)&wqh, g_wqh);
    cudaGetSymbolAddress((void**)&wql, g_wql);
    cudaGetSymbolAddress((void**)&wkh, g_wkh);
    cudaGetSymbolAddress((void**)&wkl, g_wkl);
    cudaGetSymbolAddress((void**)&wvh, g_wvh);
    cudaGetSymbolAddress((void**)&wvl, g_wvl);
    cudaGetSymbolAddress((void**)&woh, g_woh);
    cudaGetSymbolAddress((void**)&wol, g_wol);
    cudaGetSymbolAddress((void**)&ohi, g_ohi);
    cudaGetSymbolAddress((void**)&olo, g_olo);
    cudaGetSymbolAddress((void**)&qhv, g_qh);
    cudaGetSymbolAddress((void**)&qlv, g_ql);
    cudaGetSymbolAddress((void**)&k2h, g_k2h);
    cudaGetSymbolAddress((void**)&k2l, g_k2l);
    cudaGetSymbolAddress((void**)&vth, g_vth);
    cudaGetSymbolAddress((void**)&vtl, g_vtl);

    cudaFuncSetAttribute(gemm_bf16x3, cudaFuncAttributeMaxDynamicSharedMemorySize, GEMM_SMEM);
    cudaFuncSetAttribute(attn_stats_mma, cudaFuncAttributeMaxDynamicSharedMemorySize, P1_SMEM);
    cudaFuncSetAttribute(attn_pv_mma, cudaFuncAttributeMaxDynamicSharedMemorySize, P2_SMEM);

    // weight transpose + split, hidden split
    transpose_split<<<dim3(4096 / 32, KK_ / 32), dim3(32, 8)>>>(Wq, wqh, wql, 4096);
    transpose_split<<<dim3(512 / 32,  KK_ / 32), dim3(32, 8)>>>(Wk, wkh, wkl, 512);
    transpose_split<<<dim3(512 / 32,  KK_ / 32), dim3(32, 8)>>>(Wv, wvh, wvl, 512);
    transpose_split<<<dim3(2048 / 32, KK_ / 32), dim3(32, 8)>>>(Wo, woh, wol, 2048);
    {
        int n4 = (int)((size_t)MT_ * KK_ / 4);
        split_bf16<<<(n4 + 255) / 256, 256>>>(hidden, ahi, alo, n4);
    }

    // projections (HMMA bf16x3)
    gemm_bf16x3<<<dim3(4096 / 128, MT_ / 128), 256, GEMM_SMEM>>>(ahi, alo, wqh, wql, qg, 4096);
    gemm_bf16x3<<<dim3(512 / 128,  MT_ / 128), 256, GEMM_SMEM>>>(ahi, alo, wkh, wkl, ktmp, 512);
    gemm_bf16x3<<<dim3(512 / 128,  MT_ / 128), 256, GEMM_SMEM>>>(ahi, alo, wvh, wvl, vbuf, 512);

    // norm + rope -> bf16 hi/lo; V -> transposed bf16 hi/lo
    norm_rope_q_bf<<<B_ * S_ * NH_, 128>>>(qg, cosb, sinb, qnw, qhv, qlv);
    norm_rope_k_bf<<<B_ * S_ * NKV_, 128>>>(ktmp, cosb, sinb, knw, k2h, k2l);
    v_split_trans<<<dim3(S_ / 32, D_ / 32, B_ * NKV_), dim3(32, 8)>>>(vbuf, vth, vtl);

    // attention (HMMA two-pass)
    attn_stats_mma<<<dim3(S_ / 128, B_ * NH_), 256, P1_SMEM>>>(qhv, qlv, k2h, k2l, rmax, rsum);
    attn_pv_mma<<<dim3(S_ / 128, B_ * NH_), 256, P2_SMEM>>>(qhv, qlv, k2h, k2l, vth, vtl,
                                                            rmax, rsum, P, octx);
    zero_upper<<<B_ * NH_ * S_, 128>>>(P);

    // gate + output projection
    gate_mul<<<(int)(((size_t)MT_ * 2048 / 4) / 256), 256>>>(qg, octx);
    {
        int n4 = (int)((size_t)MT_ * 2048 / 4);
        split_bf16<<<(n4 + 255) / 256, 256>>>(octx, ohi, olo, n4);
    }
    gemm_bf16x3<<<dim3(2048 / 128, MT_ / 128), 256, GEMM_SMEM>>>(ohi, olo, woh, wol, out, 2048);
}

// round 5
// speedup vs baseline: 4.5434x; 1.0622x over previous
#include <cuda_runtime.h>
#include <cuda_bf16.h>
#include <cstdint>

#define B_  4
#define S_  2048
#define HID_ 2048
#define NH_ 16
#define NKV_ 4
#define D_  128
#define EPS_ 1e-6f
#define SCALE_ 0.08838834764831845f   // 128^-0.5
#define MAXB_ 11.5f                   // rigorous score bound: sqrt(128)*sqrt(128)*SCALE=11.314

#define MT_  8192     // B*S rows
#define KK_  2048     // GEMM K (always HID_)

// ---------------- scratch (static __device__, allocation-free) ----------------
__device__ float g_qg  [(size_t)MT_*4096];         // (b,s,h,2D)
__device__ float g_ktmp[(size_t)MT_*512];          // (b,s,kh,d)
__device__ float g_v   [(size_t)MT_*512];          // (b,s,kh,d)
__device__ float g_octx[(size_t)MT_*2048];         // (b,s,h,d)
__device__ float g_rowsum[(size_t)B_*NH_*S_];
// bf16 hi/lo split buffers
__device__ __nv_bfloat16 g_ahi[(size_t)MT_*KK_],  g_alo[(size_t)MT_*KK_];
__device__ __nv_bfloat16 g_wqh[(size_t)4096*KK_], g_wql[(size_t)4096*KK_];
__device__ __nv_bfloat16 g_wkh[(size_t)512*KK_],  g_wkl[(size_t)512*KK_];
__device__ __nv_bfloat16 g_wvh[(size_t)512*KK_],  g_wvl[(size_t)512*KK_];
__device__ __nv_bfloat16 g_woh[(size_t)2048*KK_], g_wol[(size_t)2048*KK_];
__device__ __nv_bfloat16 g_ohi[(size_t)MT_*2048], g_olo[(size_t)MT_*2048];
// attention bf16 operands
__device__ __nv_bfloat16 g_qh[(size_t)B_*NH_*S_*D_],  g_ql[(size_t)B_*NH_*S_*D_];
__device__ __nv_bfloat16 g_k2h[(size_t)B_*NKV_*S_*D_], g_k2l[(size_t)B_*NKV_*S_*D_];
__device__ __nv_bfloat16 g_vth[(size_t)B_*NKV_*D_*S_], g_vtl[(size_t)B_*NKV_*D_*S_];

// ================= PTX helpers (family-target-safe: sm_80+ features only) =====
__device__ __forceinline__ uint32_t smem_u32(const void* p) {
    uint32_t a;
    asm("{ .reg .u64 t; cvta.to.shared.u64 t, %1; cvt.u32.u64 %0, t; }" : "=r"(a) : "l"(p));
    return a;
}
__device__ __forceinline__ void cp16(uint32_t s, const void* g) {
    asm volatile("cp.async.cg.shared.global [%0], [%1], 16;" :: "r"(s), "l"(g));
}
__device__ __forceinline__ void ldm4(uint32_t* r, uint32_t addr) {
    asm volatile("ldmatrix.sync.aligned.m8n8.x4.shared.b16 {%0,%1,%2,%3}, [%4];"
                 : "=r"(r[0]), "=r"(r[1]), "=r"(r[2]), "=r"(r[3]) : "r"(addr));
}
__device__ __forceinline__ void mma_bf16(float* c, const uint32_t* a, const uint32_t* b) {
    asm volatile("mma.sync.aligned.m16n8k16.row.col.f32.bf16.bf16.f32 "
                 "{%0,%1,%2,%3}, {%4,%5,%6,%7}, {%8,%9}, {%0,%1,%2,%3};"
                 : "+f"(c[0]), "+f"(c[1]), "+f"(c[2]), "+f"(c[3])
                 : "r"(a[0]), "r"(a[1]), "r"(a[2]), "r"(a[3]), "r"(b[0]), "r"(b[1]));
}
// swizzled smem offsets: 128B rows (8 chunks) and 256B rows (16 chunks)
__device__ __forceinline__ uint32_t phys(int r, int c) {
    return (uint32_t)(r * 128 + ((c ^ (r & 7)) << 4));
}
__device__ __forceinline__ uint32_t phys256(int r, int c) {
    return (uint32_t)(r * 256 + (((c & 7) ^ (r & 7)) << 4) + ((c & 8) << 4));
}
__device__ __forceinline__ void split_pack(float a, float b, uint32_t& hi, uint32_t& lo) {
    __nv_bfloat16 ha = __float2bfloat16(a), hb = __float2bfloat16(b);
    __nv_bfloat16 la = __float2bfloat16(a - __bfloat162float(ha));
    __nv_bfloat16 lb = __float2bfloat16(b - __bfloat162float(hb));
    __nv_bfloat162 H(ha, hb), L(la, lb);
    hi = *(uint32_t*)&H;
    lo = *(uint32_t*)&L;
}

#define STG_BYTES 65536          // per pipeline stage: Ahi|Alo|Bhi|Blo, 16KB each
#define GEMM_SMEM (3 * STG_BYTES)

// ======= HMMA bf16x3-split GEMM: C[M,N] = A[M,K] * Bt[N,K]^T, 3-stage pipe ====
__global__ __launch_bounds__(256, 1) void gemm_bf16x3(
    const __nv_bfloat16* __restrict__ Ahi, const __nv_bfloat16* __restrict__ Alo,
    const __nv_bfloat16* __restrict__ Bhi, const __nv_bfloat16* __restrict__ Blo,
    float* __restrict__ C, int N) {
    extern __shared__ char smem[];
    const uint32_t sb = smem_u32(smem);
    const int tid = threadIdx.x, wid = tid >> 5, lane = tid & 31;
    const int m0 = blockIdx.y * 128, n0 = blockIdx.x * 128;
    const int NKI = KK_ / 64;    // 32 iters

    const __nv_bfloat16* ah = Ahi + (size_t)m0 * KK_;
    const __nv_bfloat16* al = Alo + (size_t)m0 * KK_;
    const __nv_bfloat16* bh = Bhi + (size_t)n0 * KK_;
    const __nv_bfloat16* bl = Blo + (size_t)n0 * KK_;

    auto load_stage = [&](int st, int it) {
        const uint32_t base = sb + st * STG_BYTES;
        const int k0 = it * 64;
        for (int q = tid; q < 4096; q += 256) {
            int reg = q >> 10, qq = q & 1023;
            int r = qq >> 3, c = qq & 7;
            const __nv_bfloat16* src;
            switch (reg) {
                case 0: src = ah; break;
                case 1: src = al; break;
                case 2: src = bh; break;
                default: src = bl; break;
            }
            cp16(base + reg * 16384 + phys(r, c), src + (size_t)r * KK_ + k0 + c * 8);
        }
        asm volatile("cp.async.commit_group;" ::: "memory");
    };

    load_stage(0, 0);
    load_stage(1, 1);
    load_stage(2, 2);

    const int wm = (wid & 3) * 32;
    const int wn = (wid >> 2) * 64;
    float acc[2][8][4];
#pragma unroll
    for (int i = 0; i < 2; i++)
#pragma unroll
        for (int j = 0; j < 8; j++)
#pragma unroll
            for (int q = 0; q < 4; q++) acc[i][j][q] = 0.0f;

    const int fr = (lane & 7) + ((lane >> 3) & 1) * 8;
    const int fc = lane >> 4;

    for (int i = 0; i < NKI; i++) {
        if (i < NKI - 2)       asm volatile("cp.async.wait_group 2;" ::: "memory");
        else if (i == NKI - 2) asm volatile("cp.async.wait_group 1;" ::: "memory");
        else                   asm volatile("cp.async.wait_group 0;" ::: "memory");
        __syncthreads();

        const int st = i % 3;
        const uint32_t bA = sb + st * STG_BYTES;
        const uint32_t bAl = bA + 16384, bB = bA + 32768, bBl = bA + 49152;
#pragma unroll
        for (int s = 0; s < 4; s++) {
            uint32_t ahf[2][4], alf[2][4], bhf[8][2], blf[8][2];
#pragma unroll
            for (int mi = 0; mi < 2; mi++) {
                int r = wm + mi * 16 + fr;
                uint32_t off = phys(r, s * 2 + fc);
                ldm4(ahf[mi], bA + off);
                ldm4(alf[mi], bAl + off);
            }
#pragma unroll
            for (int ng = 0; ng < 4; ng++) {
                int r = wn + ng * 16 + fr;
                uint32_t off = phys(r, s * 2 + fc);
                uint32_t t[4];
                ldm4(t, bB + off);
                bhf[ng * 2][0] = t[0]; bhf[ng * 2][1] = t[2];
                bhf[ng * 2 + 1][0] = t[1]; bhf[ng * 2 + 1][1] = t[3];
                ldm4(t, bBl + off);
                blf[ng * 2][0] = t[0]; blf[ng * 2][1] = t[2];
                blf[ng * 2 + 1][0] = t[1]; blf[ng * 2 + 1][1] = t[3];
            }
#pragma unroll
            for (int mi = 0; mi < 2; mi++)
#pragma unroll
                for (int n = 0; n < 8; n++) {
                    mma_bf16(acc[mi][n], ahf[mi], bhf[n]);
                    mma_bf16(acc[mi][n], ahf[mi], blf[n]);
                    mma_bf16(acc[mi][n], alf[mi], bhf[n]);
                }
        }
        __syncthreads();
        if (i + 3 < NKI) load_stage(st, i + 3);
    }

#pragma unroll
    for (int mi = 0; mi < 2; mi++) {
        int r0 = m0 + wm + mi * 16 + (lane >> 2);
#pragma unroll
        for (int n = 0; n < 8; n++) {
            int col = n0 + wn + n * 8 + (lane & 3) * 2;
            *(float2*)(C + (size_t)r0 * N + col)       = make_float2(acc[mi][n][0], acc[mi][n][1]);
            *(float2*)(C + (size_t)(r0 + 8) * N + col) = make_float2(acc[mi][n][2], acc[mi][n][3]);
        }
    }
}

// ============ fp32 -> bf16 hi/lo split ============
__global__ __launch_bounds__(256) void split_bf16(const float* __restrict__ x,
                                                  __nv_bfloat16* __restrict__ hi,
                                                  __nv_bfloat16* __restrict__ lo,
                                                  int n4) {
    int i = blockIdx.x * 256 + threadIdx.x;
    if (i >= n4) return;
    float4 v = ((const float4*)x)[i];
    __nv_bfloat16 h0 = __float2bfloat16(v.x), h1 = __float2bfloat16(v.y);
    __nv_bfloat16 h2 = __float2bfloat16(v.z), h3 = __float2bfloat16(v.w);
    __nv_bfloat16 l0 = __float2bfloat16(v.x - __bfloat162float(h0));
    __nv_bfloat16 l1 = __float2bfloat16(v.y - __bfloat162float(h1));
    __nv_bfloat16 l2 = __float2bfloat16(v.z - __bfloat162float(h2));
    __nv_bfloat16 l3 = __float2bfloat16(v.w - __bfloat162float(h3));
    ((__nv_bfloat162*)hi)[2 * i]     = __nv_bfloat162(h0, h1);
    ((__nv_bfloat162*)hi)[2 * i + 1] = __nv_bfloat162(h2, h3);
    ((__nv_bfloat162*)lo)[2 * i]     = __nv_bfloat162(l0, l1);
    ((__nv_bfloat162*)lo)[2 * i + 1] = __nv_bfloat162(l2, l3);
}

// ============ gate: (octx * sigmoid(gate)) -> bf16 hi/lo ============
__global__ __launch_bounds__(256) void gate_split(const float* __restrict__ qg,
                                                  const float* __restrict__ octx,
                                                  __nv_bfloat16* __restrict__ hi,
                                                  __nv_bfloat16* __restrict__ lo) {
    size_t i4 = (size_t)blockIdx.x * blockDim.x + threadIdx.x;
    size_t e = i4 * 4;
    int d = (int)(e % D_);
    int h = (int)((e / D_) % NH_);
    size_t bs = e / (D_ * NH_);
    const float4 gv = *(const float4*)(qg + (bs * NH_ + h) * (2 * D_) + D_ + d);
    float4 ov = *(const float4*)(octx + e);
    ov.x *= 1.0f / (1.0f + __expf(-gv.x));
    ov.y *= 1.0f / (1.0f + __expf(-gv.y));
    ov.z *= 1.0f / (1.0f + __expf(-gv.z));
    ov.w *= 1.0f / (1.0f + __expf(-gv.w));
    uint32_t h01, l01, h23, l23;
    split_pack(ov.x, ov.y, h01, l01);
    split_pack(ov.z, ov.w, h23, l23);
    ((uint32_t*)hi)[2 * i4]     = h01;
    ((uint32_t*)hi)[2 * i4 + 1] = h23;
    ((uint32_t*)lo)[2 * i4]     = l01;
    ((uint32_t*)lo)[2 * i4 + 1] = l23;
}

// ============ W[K,N] fp32 -> Wt hi/lo bf16 [N,K] ============
__global__ __launch_bounds__(256) void transpose_split(const float* __restrict__ W,
                                                       __nv_bfloat16* __restrict__ thi,
                                                       __nv_bfloat16* __restrict__ tlo,
                                                       int N) {
    __shared__ float t[32][33];
    const int n0 = blockIdx.x * 32, k0 = blockIdx.y * 32;
    const int tx = threadIdx.x, ty = threadIdx.y;
    for (int i = ty; i < 32; i += 8)
        t[i][tx] = W[(size_t)(k0 + i) * N + n0 + tx];
    __syncthreads();
    for (int i = ty; i < 32; i += 8) {
        float v = t[tx][i];
        __nv_bfloat16 h = __float2bfloat16(v);
        __nv_bfloat16 l = __float2bfloat16(v - __bfloat162float(h));
        thi[(size_t)(n0 + i) * KK_ + k0 + tx] = h;
        tlo[(size_t)(n0 + i) * KK_ + k0 + tx] = l;
    }
}

// ============ V fp32 (b,s,kh,d) -> V^T hi/lo bf16 (b,kh,d,s) ============
__global__ __launch_bounds__(256) void v_split_trans(const float* __restrict__ v,
                                                     __nv_bfloat16* __restrict__ vth,
                                                     __nv_bfloat16* __restrict__ vtl) {
    __shared__ float t[32][33];
    const int bk = blockIdx.z;
    const int b = bk >> 2, kv = bk & 3;
    const int s0 = blockIdx.x * 32, d0 = blockIdx.y * 32;
    const int tx = threadIdx.x, ty = threadIdx.y;
    for (int i = ty; i < 32; i += 8)
        t[i][tx] = v[((size_t)(b * S_ + s0 + i) * NKV_ + kv) * D_ + d0 + tx];
    __syncthreads();
    for (int i = ty; i < 32; i += 8) {
        float val = t[tx][i];
        __nv_bfloat16 h = __float2bfloat16(val);
        __nv_bfloat16 l = __float2bfloat16(val - __bfloat162float(h));
        size_t o = ((size_t)(b * NKV_ + kv) * D_ + d0 + i) * S_ + s0 + tx;
        vth[o] = h;
        vtl[o] = l;
    }
}

// ---------------- RMSNorm + RoPE -> bf16 hi/lo ----------------
__global__ __launch_bounds__(128) void norm_rope_q_bf(const float* __restrict__ qg,
                                                      const float* __restrict__ cosb,
                                                      const float* __restrict__ sinb,
                                                      const float* __restrict__ w,
                                                      __nv_bfloat16* __restrict__ qh,
                                                      __nv_bfloat16* __restrict__ ql) {
    const int idx = blockIdx.x;
    const int h = idx % NH_;
    const int bs = idx / NH_;
    const int d = threadIdx.x;
    const float* x = qg + ((size_t)bs * NH_ + h) * (2 * D_);
    float xv = x[d];
    float sq = xv * xv;
#pragma unroll
    for (int o = 16; o > 0; o >>= 1) sq += __shfl_xor_sync(0xffffffffu, sq, o);
    __shared__ float wsum[4];
    __shared__ float xs[D_];
    if ((d & 31) == 0) wsum[d >> 5] = sq;
    __syncthreads();
    float total = wsum[0] + wsum[1] + wsum[2] + wsum[3];
    float xn = xv * rsqrtf(total * (1.0f / D_) + EPS_) * (1.0f + w[d]);
    xs[d] = xn;
    __syncthreads();
    float c = cosb[(size_t)bs * D_ + d];
    float sn = sinb[(size_t)bs * D_ + d];
    float rot = (d < D_ / 2) ? -xs[d + D_ / 2] : xs[d - D_ / 2];
    float val = xn * c + rot * sn;
    const int b = bs / S_, s = bs % S_;
    size_t o = (((size_t)b * NH_ + h) * S_ + s) * D_ + d;
    __nv_bfloat16 hi = __float2bfloat16(val);
    qh[o] = hi;
    ql[o] = __float2bfloat16(val - __bfloat162float(hi));
}

__global__ __launch_bounds__(128) void norm_rope_k_bf(const float* __restrict__ kin,
                                                      const float* __restrict__ cosb,
                                                      const float* __restrict__ sinb,
                                                      const float* __restrict__ w,
                                                      __nv_bfloat16* __restrict__ kh,
                                                      __nv_bfloat16* __restrict__ kl) {
    const int idx = blockIdx.x;
    const int kv = idx % NKV_;
    const int bs = idx / NKV_;
    const int d = threadIdx.x;
    const float* x = kin + ((size_t)bs * NKV_ + kv) * D_;
    float xv = x[d];
    float sq = xv * xv;
#pragma unroll
    for (int o = 16; o > 0; o >>= 1) sq += __shfl_xor_sync(0xffffffffu, sq, o);
    __shared__ float wsum[4];
    __shared__ float xs[D_];
    if ((d & 31) == 0) wsum[d >> 5] = sq;
    __syncthreads();
    float total = wsum[0] + wsum[1] + wsum[2] + wsum[3];
    float xn = xv * rsqrtf(total * (1.0f / D_) + EPS_) * (1.0f + w[d]);
    xs[d] = xn;
    __syncthreads();
    float c = cosb[(size_t)bs * D_ + d];
    float sn = sinb[(size_t)bs * D_ + d];
    float rot = (d < D_ / 2) ? -xs[d + D_ / 2] : xs[d - D_ / 2];
    float val = xn * c + rot * sn;
    const int b = bs / S_, s = bs % S_;
    size_t o = (((size_t)b * NKV_ + kv) * S_ + s) * D_ + d;
    __nv_bfloat16 hi = __float2bfloat16(val);
    kh[o] = hi;
    kl[o] = __float2bfloat16(val - __bfloat162float(hi));
}

// ============== single-pass fused attention: fixed-max softmax ==============
// Writes UNNORMALIZED exp(s - MAXB) to P, rowsum to l, normalized octx.
// smem: Q 64KB + 2 stages of (Khi,Klo,Vhi,Vlo) 64KB each = 192KB
#define P2_SMEM 196608
__global__ __launch_bounds__(256, 1) void attn_fused(
    const __nv_bfloat16* __restrict__ qh, const __nv_bfloat16* __restrict__ ql,
    const __nv_bfloat16* __restrict__ khb, const __nv_bfloat16* __restrict__ klb,
    const __nv_bfloat16* __restrict__ vth, const __nv_bfloat16* __restrict__ vtl,
    float* __restrict__ rowsum,
    float* __restrict__ P, float* __restrict__ octx) {
    extern __shared__ char smem[];
    const uint32_t sb = smem_u32(smem);
    const int tid = threadIdx.x, wid = tid >> 5, lane = tid & 31;
    const int qt = blockIdx.x, bh = blockIdx.y;
    const int b = bh >> 4, h = bh & 15, kv = h >> 2;
    const int q0 = qt * 128;
    const int nk = 2 * qt + 2;
    const __nv_bfloat16* qhp = qh + ((size_t)(b * NH_ + h) * S_ + q0) * D_;
    const __nv_bfloat16* qlp = ql + ((size_t)(b * NH_ + h) * S_ + q0) * D_;
    const __nv_bfloat16* khp = khb + (size_t)(b * NKV_ + kv) * S_ * D_;
    const __nv_bfloat16* klp = klb + (size_t)(b * NKV_ + kv) * S_ * D_;
    const __nv_bfloat16* vhp = vth + (size_t)(b * NKV_ + kv) * D_ * S_;
    const __nv_bfloat16* vlp = vtl + (size_t)(b * NKV_ + kv) * D_ * S_;

    for (int q = tid; q < 2048; q += 256) {
        int r = q >> 4, c = q & 15;
        uint32_t off = phys256(r, c);
        cp16(sb + off, qhp + (size_t)r * D_ + c * 8);
        cp16(sb + 32768 + off, qlp + (size_t)r * D_ + c * 8);
    }
    auto load_stage = [&](int st, int kt) {
        uint32_t base = sb + 65536 + st * 65536;
        const __nv_bfloat16* sh = khp + (size_t)kt * 64 * D_;
        const __nv_bfloat16* sl = klp + (size_t)kt * 64 * D_;
        for (int q = tid; q < 1024; q += 256) {
            int r = q >> 4, c = q & 15;
            uint32_t off = phys256(r, c);
            cp16(base + off, sh + (size_t)r * D_ + c * 8);
            cp16(base + 16384 + off, sl + (size_t)r * D_ + c * 8);
        }
        for (int q = tid; q < 1024; q += 256) {
            int r = q >> 3, c = q & 7;
            uint32_t off = phys(r, c);
            cp16(base + 32768 + off, vhp + (size_t)r * S_ + kt * 64 + c * 8);
            cp16(base + 49152 + off, vlp + (size_t)r * S_ + kt * 64 + c * 8);
        }
    };
    load_stage(0, 0);
    asm volatile("cp.async.commit_group;" ::: "memory");
    load_stage(1, 1);
    asm volatile("cp.async.commit_group;" ::: "memory");

    const int wm = (wid & 3) * 32, wn = (wid >> 2) * 32;
    const int fr = (lane & 7) + ((lane >> 3) & 1) * 8;
    const int fc = lane >> 4;

    float lsum[4] = {0.0f, 0.0f, 0.0f, 0.0f};
    float pv[2][16][4];
#pragma unroll
    for (int mi = 0; mi < 2; mi++)
#pragma unroll
        for (int n = 0; n < 16; n++)
#pragma unroll
            for (int q = 0; q < 4; q++) pv[mi][n][q] = 0.0f;

    for (int kt = 0; kt < nk; kt++) {
        if (kt == nk - 1) asm volatile("cp.async.wait_group 0;" ::: "memory");
        else              asm volatile("cp.async.wait_group 1;" ::: "memory");
        __syncthreads();
        const uint32_t stg = sb + 65536 + (kt & 1) * 65536;
        const uint32_t bK = stg, bKl = stg + 16384, bV = stg + 32768, bVl = stg + 49152;

        float acc[2][4][4];
#pragma unroll
        for (int i = 0; i < 2; i++)
#pragma unroll
            for (int j = 0; j < 4; j++)
#pragma unroll
                for (int q = 0; q < 4; q++) acc[i][j][q] = 0.0f;

#pragma unroll
        for (int ks = 0; ks < 8; ks++) {
            uint32_t ahf[2][4], alf[2][4], bhf[4][2], blf[4][2];
#pragma unroll
            for (int mi = 0; mi < 2; mi++) {
                uint32_t off = phys256(wm + mi * 16 + fr, ks * 2 + fc);
                ldm4(ahf[mi], sb + off);
                ldm4(alf[mi], sb + 32768 + off);
            }
#pragma unroll
            for (int ng = 0; ng < 2; ng++) {
                uint32_t off = phys256(wn + ng * 16 + fr, ks * 2 + fc);
                uint32_t t[4];
                ldm4(t, bK + off);
                bhf[ng * 2][0] = t[0]; bhf[ng * 2][1] = t[2];
                bhf[ng * 2 + 1][0] = t[1]; bhf[ng * 2 + 1][1] = t[3];
                ldm4(t, bKl + off);
                blf[ng * 2][0] = t[0]; blf[ng * 2][1] = t[2];
                blf[ng * 2 + 1][0] = t[1]; blf[ng * 2 + 1][1] = t[3];
            }
#pragma unroll
            for (int mi = 0; mi < 2; mi++)
#pragma unroll
                for (int n = 0; n < 4; n++) {
                    mma_bf16(acc[mi][n], ahf[mi], bhf[n]);
                    mma_bf16(acc[mi][n], ahf[mi], blf[n]);
                    mma_bf16(acc[mi][n], alf[mi], bhf[n]);
                }
        }

        // e = exp(s*SCALE - MAXB)  (masked -> 0); accumulate rowsum; write P
        const bool full = (kt * 64 + 63 <= q0);
#pragma unroll
        for (int mi = 0; mi < 2; mi++)
#pragma unroll
            for (int n = 0; n < 4; n++)
#pragma unroll
                for (int e = 0; e < 4; e++) {
                    const int slot = mi * 2 + (e >> 1);
                    float p = __expf(acc[mi][n][e] * SCALE_ - MAXB_);
                    if (!full) {
                        int gi = q0 + wm + mi * 16 + (lane >> 2) + (e >> 1) * 8;
                        int gj = kt * 64 + wn + n * 8 + (lane & 3) * 2 + (e & 1);
                        if (gj > gi) p = 0.0f;
                    }
                    acc[mi][n][e] = p;
                    lsum[slot] += p;
                }
#pragma unroll
        for (int mi = 0; mi < 2; mi++) {
            int r0 = q0 + wm + mi * 16 + (lane >> 2);
#pragma unroll
            for (int n = 0; n < 4; n++) {
                int col = kt * 64 + wn + n * 8 + (lane & 3) * 2;
                *(float2*)(P + ((size_t)bh * S_ + r0) * S_ + col) =
                    make_float2(acc[mi][n][0], acc[mi][n][1]);
                *(float2*)(P + ((size_t)bh * S_ + r0 + 8) * S_ + col) =
                    make_float2(acc[mi][n][2], acc[mi][n][3]);
            }
        }

        // PV: e (as A frags, hi/lo) x V^T (B frags, hi/lo)
#pragma unroll
        for (int ksl = 0; ksl < 2; ksl++) {
            uint32_t pah[2][4], pal[2][4];
#pragma unroll
            for (int mi = 0; mi < 2; mi++) {
                const int n0 = ksl * 2, n1 = ksl * 2 + 1;
                split_pack(acc[mi][n0][0], acc[mi][n0][1], pah[mi][0], pal[mi][0]);
                split_pack(acc[mi][n0][2], acc[mi][n0][3], pah[mi][1], pal[mi][1]);
                split_pack(acc[mi][n1][0], acc[mi][n1][1], pah[mi][2], pal[mi][2]);
                split_pack(acc[mi][n1][2], acc[mi][n1][3], pah[mi][3], pal[mi][3]);
            }
            const int cc = (wn >> 3) + ksl * 2;
#pragma unroll
            for (int dg = 0; dg < 8; dg++) {
                uint32_t t[4], bh2[2][2], bl2[2][2];
                uint32_t off = phys(dg * 16 + fr, cc + fc);
                ldm4(t, bV + off);
                bh2[0][0] = t[0]; bh2[0][1] = t[2];
                bh2[1][0] = t[1]; bh2[1][1] = t[3];
                ldm4(t, bVl + off);
                bl2[0][0] = t[0]; bl2[0][1] = t[2];
                bl2[1][0] = t[1]; bl2[1][1] = t[3];
#pragma unroll
                for (int mi = 0; mi < 2; mi++)
#pragma unroll
                    for (int sub = 0; sub < 2; sub++) {
                        const int nf = dg * 2 + sub;
                        mma_bf16(pv[mi][nf], pah[mi], bh2[sub]);
                        mma_bf16(pv[mi][nf], pah[mi], bl2[sub]);
                        mma_bf16(pv[mi][nf], pal[mi], bh2[sub]);
                    }
            }
        }
        __syncthreads();
        if (kt + 2 < nk) {
            load_stage(kt & 1, kt + 2);
            asm volatile("cp.async.commit_group;" ::: "memory");
        }
    }

    // reduce lsum across the 4 lanes of each quad (they hold different cols of same row)
#pragma unroll
    for (int o = 1; o < 4; o <<= 1)
#pragma unroll
        for (int slot = 0; slot < 4; slot++)
            lsum[slot] += __shfl_xor_sync(0xffffffffu, lsum[slot], o);

    // combine the two col-warp groups; normalize; store octx + rowsum
    __syncthreads();
    float* ob = (float*)smem;          // 128 rows x pitch 136 floats
    float* lrow = ob + 128 * 136;      // 128 partial row sums from group 1
    if (wn == 32) {
#pragma unroll
        for (int mi = 0; mi < 2; mi++) {
            int r0 = wm + mi * 16 + (lane >> 2);
#pragma unroll
            for (int nf = 0; nf < 16; nf++) {
                int d = nf * 8 + (lane & 3) * 2;
                *(float2*)&ob[(size_t)r0 * 136 + d]       = make_float2(pv[mi][nf][0], pv[mi][nf][1]);
                *(float2*)&ob[(size_t)(r0 + 8) * 136 + d] = make_float2(pv[mi][nf][2], pv[mi][nf][3]);
            }
            if ((lane & 3) == 0) {
                lrow[r0]     = lsum[mi * 2];
                lrow[r0 + 8] = lsum[mi * 2 + 1];
            }
        }
    }
    __syncthreads();
    if (wn == 0) {
#pragma unroll
        for (int mi = 0; mi < 2; mi++) {
            int r0 = wm + mi * 16 + (lane >> 2);
            float lt0 = lsum[mi * 2] + lrow[r0];
            float lt1 = lsum[mi * 2 + 1] + lrow[r0 + 8];
            float inv0 = 1.0f / lt0;
            float inv1 = 1.0f / lt1;
            if ((lane & 3) == 0) {
                rowsum[(size_t)bh * S_ + q0 + r0]     = lt0;
                rowsum[(size_t)bh * S_ + q0 + r0 + 8] = lt1;
            }
#pragma unroll
            for (int nf = 0; nf < 16; nf++) {
                int d = nf * 8 + (lane & 3) * 2;
                float2 a0 = *(float2*)&ob[(size_t)r0 * 136 + d];
                float2 a1 = *(float2*)&ob[(size_t)(r0 + 8) * 136 + d];
                float* o0 = octx + ((size_t)(b * S_ + q0 + r0) * NH_ + h) * D_ + d;
                float* o1 = octx + ((size_t)(b * S_ + q0 + r0 + 8) * NH_ + h) * D_ + d;
                *(float2*)o0 = make_float2((pv[mi][nf][0] + a0.x) * inv0, (pv[mi][nf][1] + a0.y) * inv0);
                *(float2*)o1 = make_float2((pv[mi][nf][2] + a1.x) * inv1, (pv[mi][nf][3] + a1.y) * inv1);
            }
        }
    }
}

// -------- fixup: normalize written P region by 1/rowsum, zero the rest --------
__global__ __launch_bounds__(128) void normalize_zero(float* __restrict__ P,
                                                      const float* __restrict__ rowsum) {
    const int row = blockIdx.x;          // bh*S + i
    const int i = row & (S_ - 1);
    const int jend = ((i >> 7) + 1) << 7;           // written region length
    const float inv = 1.0f / rowsum[row];
    float* p = P + (size_t)row * S_;
    const int t4 = threadIdx.x * 4;
    for (int j = t4; j < jend; j += 512) {
        float4 v = *(float4*)(p + j);
        v.x *= inv; v.y *= inv; v.z *= inv; v.w *= inv;
        *(float4*)(p + j) = v;
    }
    const float4 z = {0, 0, 0, 0};
    for (int j = jend + t4; j < S_; j += 512)
        *(float4*)(p + j) = z;
}

// ---------------- launch ----------------
extern "C" void kernel_launch(void* const* d_in, const int* in_sizes, int n_in,
                              void* d_out, int out_size) {
    const float* hidden = (const float*)d_in[0];
    const float* cosb   = (const float*)d_in[1];
    const float* sinb   = (const float*)d_in[2];
    const float* Wq     = (const float*)d_in[4];
    const float* Wk     = (const float*)d_in[5];
    const float* Wv     = (const float*)d_in[6];
    const float* Wo     = (const float*)d_in[7];
    const float* qnw    = (const float*)d_in[8];
    const float* knw    = (const float*)d_in[9];

    float* out = (float*)d_out;
    const size_t ao_elems = (size_t)MT_ * HID_;
    float* P = out + ao_elems;

    float *qg, *ktmp, *vbuf, *octx, *rsum;
    __nv_bfloat16 *ahi, *alo, *wqh, *wql, *wkh, *wkl, *wvh, *wvl, *woh, *wol, *ohi, *olo;
    __nv_bfloat16 *qhv, *qlv, *k2h, *k2l, *vth, *vtl;
    cudaGetSymbolAddress((void**)&qg,   g_qg);
    cudaGetSymbolAddress((void**)&ktmp, g_ktmp);
    cudaGetSymbolAddress((void**)&vbuf, g_v);
    cudaGetSymbolAddress((void**)&octx, g_octx);
    cudaGetSymbolAddress((void**)&rsum, g_rowsum);
    cudaGetSymbolAddress((void**)&ahi, g_ahi);
    cudaGetSymbolAddress((void**)&alo, g_alo);
    cudaGetSymbolAddress((void**)&wqh, g_wqh);
    cudaGetSymbolAddress((void**)&wql, g_wql);
    cudaGetSymbolAddress((void**)&wkh, g_wkh);
    cudaGetSymbolAddress((void**)&wkl, g_wkl);
    cudaGetSymbolAddress((void**)&wvh, g_wvh);
    cudaGetSymbolAddress((void**)&wvl, g_wvl);
    cudaGetSymbolAddress((void**)&woh, g_woh);
    cudaGetSymbolAddress((void**)&wol, g_wol);
    cudaGetSymbolAddress((void**)&ohi, g_ohi);
    cudaGetSymbolAddress((void**)&olo, g_olo);
    cudaGetSymbolAddress((void**)&qhv, g_qh);
    cudaGetSymbolAddress((void**)&qlv, g_ql);
    cudaGetSymbolAddress((void**)&k2h, g_k2h);
    cudaGetSymbolAddress((void**)&k2l, g_k2l);
    cudaGetSymbolAddress((void**)&vth, g_vth);
    cudaGetSymbolAddress((void**)&vtl, g_vtl);

    cudaFuncSetAttribute(gemm_bf16x3, cudaFuncAttributeMaxDynamicSharedMemorySize, GEMM_SMEM);
    cudaFuncSetAttribute(attn_fused, cudaFuncAttributeMaxDynamicSharedMemorySize, P2_SMEM);

    // weight transpose + split, hidden split
    transpose_split<<<dim3(4096 / 32, KK_ / 32), dim3(32, 8)>>>(Wq, wqh, wql, 4096);
    transpose_split<<<dim3(512 / 32,  KK_ / 32), dim3(32, 8)>>>(Wk, wkh, wkl, 512);
    transpose_split<<<dim3(512 / 32,  KK_ / 32), dim3(32, 8)>>>(Wv, wvh, wvl, 512);
    transpose_split<<<dim3(2048 / 32, KK_ / 32), dim3(32, 8)>>>(Wo, woh, wol, 2048);
    {
        int n4 = (int)((size_t)MT_ * KK_ / 4);
        split_bf16<<<(n4 + 255) / 256, 256>>>(hidden, ahi, alo, n4);
    }

    // projections (HMMA bf16x3, 3-stage)
    gemm_bf16x3<<<dim3(4096 / 128, MT_ / 128), 256, GEMM_SMEM>>>(ahi, alo, wqh, wql, qg, 4096);
    gemm_bf16x3<<<dim3(512 / 128,  MT_ / 128), 256, GEMM_SMEM>>>(ahi, alo, wkh, wkl, ktmp, 512);
    gemm_bf16x3<<<dim3(512 / 128,  MT_ / 128), 256, GEMM_SMEM>>>(ahi, alo, wvh, wvl, vbuf, 512);

    // norm + rope -> bf16 hi/lo; V -> transposed bf16 hi/lo
    norm_rope_q_bf<<<B_ * S_ * NH_, 128>>>(qg, cosb, sinb, qnw, qhv, qlv);
    norm_rope_k_bf<<<B_ * S_ * NKV_, 128>>>(ktmp, cosb, sinb, knw, k2h, k2l);
    v_split_trans<<<dim3(S_ / 32, D_ / 32, B_ * NKV_), dim3(32, 8)>>>(vbuf, vth, vtl);

    // fused single-pass attention + P normalize/zero fixup
    attn_fused<<<dim3(S_ / 128, B_ * NH_), 256, P2_SMEM>>>(qhv, qlv, k2h, k2l, vth, vtl,
                                                           rsum, P, octx);
    normalize_zero<<<B_ * NH_ * S_, 128>>>(P, rsum);

    // gate + split + output projection
    gate_split<<<(int)(((size_t)MT_ * 2048 / 4) / 256), 256>>>(qg, octx, ohi, olo);
    gemm_bf16x3<<<dim3(2048 / 128, MT_ / 128), 256, GEMM_SMEM>>>(ohi, olo, woh, wol, out, 2048);
}